// round 10
// baseline (speedup 1.0000x reference)
#include <cuda_runtime.h>
#include <cuda_bf16.h>
#include <cstdint>

#define Bb   8
#define Nn   4096
#define Mm   2048
#define DIN  256
#define DOUT 128

__device__ __nv_bfloat16 g_Qh [Bb*Mm*DOUT];
__device__ __nv_bfloat16 g_Ql [Bb*Mm*DOUT];
__device__ __nv_bfloat16 g_Kh [Bb*Mm*DOUT];
__device__ __nv_bfloat16 g_Kl [Bb*Mm*DOUT];
__device__ float         g_V  [Bb*Mm*DOUT];
__device__ __nv_bfloat16 g_Vth[Bb*DOUT*Mm];    // [b][e][m]
__device__ __nv_bfloat16 g_Vtl[Bb*DOUT*Mm];
__device__ __nv_bfloat16 g_Wth[3*DOUT*DIN];    // [wsel][n][k]
__device__ __nv_bfloat16 g_Wtl[3*DOUT*DIN];
__device__ __nv_bfloat16 g_Ah [(size_t)Bb*Mm*Mm];
__device__ __nv_bfloat16 g_Al [(size_t)Bb*Mm*Mm];

// ---------------- helpers ----------------
__device__ __forceinline__ uint32_t cvta_smem(const void* p) {
    uint32_t a;
    asm("{ .reg .u64 t; cvta.to.shared.u64 t, %1; cvt.u32.u64 %0, t; }" : "=r"(a) : "l"(p));
    return a;
}
__device__ __forceinline__ uint32_t b2pack(float a, float b) {
    uint16_t la = __bfloat16_as_ushort(__float2bfloat16(a));
    uint16_t lb = __bfloat16_as_ushort(__float2bfloat16(b));
    return (uint32_t)la | ((uint32_t)lb << 16);
}
__device__ __forceinline__ float bhi(float x) {
    return __bfloat162float(__float2bfloat16(x));
}
__device__ __forceinline__ void ldmA(uint32_t a[4], uint32_t addr) {
    asm volatile("ldmatrix.sync.aligned.m8n8.x4.shared.b16 {%0,%1,%2,%3}, [%4];"
        : "=r"(a[0]),"=r"(a[1]),"=r"(a[2]),"=r"(a[3]) : "r"(addr));
}
// x4 B-load: fragments for two adjacent j (lanes 16-31 address the j+1 rows)
__device__ __forceinline__ void ldmB4(uint32_t b[4], uint32_t addr) {
    asm volatile("ldmatrix.sync.aligned.m8n8.x4.shared.b16 {%0,%1,%2,%3}, [%4];"
        : "=r"(b[0]),"=r"(b[1]),"=r"(b[2]),"=r"(b[3]) : "r"(addr));
}
__device__ __forceinline__ void mma16816(float c[4], const uint32_t a[4], const uint32_t b[2]) {
    asm volatile("mma.sync.aligned.m16n8k16.row.col.f32.bf16.bf16.f32 "
        "{%0,%1,%2,%3}, {%4,%5,%6,%7}, {%8,%9}, {%0,%1,%2,%3};"
        : "+f"(c[0]),"+f"(c[1]),"+f"(c[2]),"+f"(c[3])
        : "r"(a[0]),"r"(a[1]),"r"(a[2]),"r"(a[3]), "r"(b[0]),"r"(b[1]));
}
#define CPA(d, s) asm volatile("cp.async.cg.shared.global [%0], [%1], 16;" :: "r"(d), "l"(s))
#define CPC()     asm volatile("cp.async.commit_group;" ::: "memory")
#define CPW1()    asm volatile("cp.async.wait_group 1;" ::: "memory")
#define CPW0()    asm volatile("cp.async.wait_group 0;" ::: "memory")

#define PIT 136
#define PITB 272
#define P64B 144

// ---------------------------------------------------------------------------
__global__ void prep_kernel(const float* __restrict__ Wq,
                            const float* __restrict__ Wk,
                            const float* __restrict__ Wv)
{
    const float* W = (blockIdx.x == 0) ? Wq : (blockIdx.x == 1) ? Wk : Wv;
    __nv_bfloat16* dh = g_Wth + blockIdx.x * DOUT * DIN;
    __nv_bfloat16* dl = g_Wtl + blockIdx.x * DOUT * DIN;
    for (int i = threadIdx.x; i < DOUT * (DIN/2); i += 256) {
        int n = i >> 7, k = (i & 127) * 2;
        float x0 = W[(size_t)k*DOUT + n];
        float x1 = W[(size_t)(k+1)*DOUT + n];
        *reinterpret_cast<uint32_t*>(dh + (size_t)n*DIN + k) = b2pack(x0, x1);
        *reinterpret_cast<uint32_t*>(dl + (size_t)n*DIN + k) =
            b2pack(x0 - bhi(x0), x1 - bhi(x1));
    }
}

// ---------------------------------------------------------------------------
// projmma: 512 threads, 16 warps (4m x 4n), warp tile 32x32 (mi=2, j=4).
// ---------------------------------------------------------------------------
__global__ __launch_bounds__(512, 1)
void projmma_kernel(const float* __restrict__ Y, const int* __restrict__ idx,
                    const float* __restrict__ bq, const float* __restrict__ bk,
                    const float* __restrict__ bv)
{
    extern __shared__ char smraw[];
    char* Ah = smraw;                    // 2 k-chunks x 34816
    char* Al = smraw + 69632;
    char* Bh = smraw + 139264;
    char* Bl = smraw + 174080;
    float* Vs = reinterpret_cast<float*>(Bh);
    __shared__ int idxs[128];

    const int tid = threadIdx.x, lane = tid & 31, wid = tid >> 5;
    const int wm = wid >> 2, wn = wid & 3;
    const int row0 = blockIdx.x * 128;
    const int b    = row0 / Mm;
    const int m0   = row0 % Mm;

    if (tid < 128) idxs[tid] = idx[b*Mm + m0 + tid];
    __syncthreads();

    for (int i = tid; i < 128*64; i += 512) {
        int row = i >> 6, c4 = i & 63;
        float4 y = *reinterpret_cast<const float4*>(
            Y + ((size_t)b*Nn + idxs[row])*DIN + c4*4);
        int kc = c4 >> 5;
        uint32_t off = (uint32_t)(kc*34816 + row*PITB + (c4 & 31)*8);
        *reinterpret_cast<uint2*>(Ah + off) =
            make_uint2(b2pack(y.x, y.y), b2pack(y.z, y.w));
        *reinterpret_cast<uint2*>(Al + off) =
            make_uint2(b2pack(y.x-bhi(y.x), y.y-bhi(y.y)),
                       b2pack(y.z-bhi(y.z), y.w-bhi(y.w)));
    }

    const uint32_t sAh = cvta_smem(Ah), sAl = cvta_smem(Al);
    const uint32_t sBh = cvta_smem(Bh), sBl = cvta_smem(Bl);

    const int aRow  = wm*32 + (lane & 15);
    const int aKb   = (lane >> 4) * 8;
    const int bRow4 = wn*32 + ((lane >> 4) << 3) + (lane & 7);
    const int bK4   = ((lane >> 3) & 1) * 8;

    #pragma unroll 1
    for (int wsel = 0; wsel < 3; wsel++) {
        float acc[2][4][4] = {};
        #pragma unroll 1
        for (int kc = 0; kc < 2; kc++) {
            __syncthreads();
            const __nv_bfloat16* wh = g_Wth + (size_t)wsel*DOUT*DIN + kc*128;
            const __nv_bfloat16* wl = g_Wtl + (size_t)wsel*DOUT*DIN + kc*128;
            for (int i = tid; i < 128*16; i += 512) {
                int n = i >> 4, c8 = i & 15;
                uint32_t off = (uint32_t)(n*PITB + c8*16);
                size_t go = (size_t)n*DIN + c8*8;
                *reinterpret_cast<uint4*>(Bh + off) =
                    *reinterpret_cast<const uint4*>(wh + go);
                *reinterpret_cast<uint4*>(Bl + off) =
                    *reinterpret_cast<const uint4*>(wl + go);
            }
            __syncthreads();
            uint32_t aBase = kc * 34816;
            #pragma unroll
            for (int term = 0; term < 3; term++) {
                uint32_t sA = ((term == 2) ? sAl : sAh) + aBase;
                uint32_t sB = (term == 1) ? sBl : sBh;
                #pragma unroll
                for (int ks = 0; ks < 8; ks++) {
                    uint32_t af[2][4];
                    #pragma unroll
                    for (int mi = 0; mi < 2; mi++)
                        ldmA(af[mi], sA + ((aRow + mi*16)*PIT + aKb + ks*16)*2);
                    #pragma unroll
                    for (int jj = 0; jj < 2; jj++) {
                        uint32_t bq4[4];
                        ldmB4(bq4, sB + ((bRow4 + jj*16)*PIT + bK4 + ks*16)*2);
                        #pragma unroll
                        for (int mi = 0; mi < 2; mi++) {
                            mma16816(acc[mi][2*jj],     af[mi], bq4);
                            mma16816(acc[mi][2*jj + 1], af[mi], bq4 + 2);
                        }
                    }
                }
            }
        }

        const float* bp = (wsel == 0) ? bq : (wsel == 1) ? bk : bv;
        float bias2[4][2];
        #pragma unroll
        for (int j = 0; j < 4; j++) {
            int c = wn*32 + j*8 + (lane & 3)*2;
            bias2[j][0] = bp[c]; bias2[j][1] = bp[c+1];
        }

        if (wsel < 2) {
            const float s = (wsel == 0) ? 0.0625f : 1.0f;
            __nv_bfloat16* gh = (wsel == 0) ? g_Qh : g_Kh;
            __nv_bfloat16* gl = (wsel == 0) ? g_Ql : g_Kl;
            #pragma unroll
            for (int mi = 0; mi < 2; mi++)
                #pragma unroll
                for (int j = 0; j < 4; j++) {
                    int r = wm*32 + mi*16 + (lane >> 2);
                    int c = wn*32 + j*8 + (lane & 3)*2;
                    float q0 = (acc[mi][j][0] + bias2[j][0]) * s;
                    float q1 = (acc[mi][j][1] + bias2[j][1]) * s;
                    float q2 = (acc[mi][j][2] + bias2[j][0]) * s;
                    float q3 = (acc[mi][j][3] + bias2[j][1]) * s;
                    size_t o0 = ((size_t)(b*Mm + m0 + r))*DOUT + c;
                    size_t o1 = ((size_t)(b*Mm + m0 + r + 8))*DOUT + c;
                    *reinterpret_cast<uint32_t*>(gh + o0) = b2pack(q0, q1);
                    *reinterpret_cast<uint32_t*>(gl + o0) =
                        b2pack(q0 - bhi(q0), q1 - bhi(q1));
                    *reinterpret_cast<uint32_t*>(gh + o1) = b2pack(q2, q3);
                    *reinterpret_cast<uint32_t*>(gl + o1) =
                        b2pack(q2 - bhi(q2), q3 - bhi(q3));
                }
        } else {
            __syncthreads();
            #pragma unroll
            for (int mi = 0; mi < 2; mi++)
                #pragma unroll
                for (int j = 0; j < 4; j++) {
                    int r = wm*32 + mi*16 + (lane >> 2);
                    int c = wn*32 + j*8 + (lane & 3)*2;
                    float v0 = fmaxf(acc[mi][j][0] + bias2[j][0], 0.f);
                    float v1 = fmaxf(acc[mi][j][1] + bias2[j][1], 0.f);
                    float v2 = fmaxf(acc[mi][j][2] + bias2[j][0], 0.f);
                    float v3 = fmaxf(acc[mi][j][3] + bias2[j][1], 0.f);
                    *reinterpret_cast<float2*>(
                        g_V + ((size_t)(b*Mm + m0 + r))*DOUT + c) = make_float2(v0, v1);
                    *reinterpret_cast<float2*>(
                        g_V + ((size_t)(b*Mm + m0 + r + 8))*DOUT + c) = make_float2(v2, v3);
                    Vs[r*132 + c]       = v0;
                    Vs[r*132 + c + 1]   = v1;
                    Vs[(r+8)*132 + c]   = v2;
                    Vs[(r+8)*132 + c+1] = v3;
                }
            __syncthreads();
            int e = tid & 127, quarter = tid >> 7;
            int mb = quarter * 32;
            uint32_t hp[16], lp[16];
            #pragma unroll
            for (int t = 0; t < 16; t++) {
                float x0 = Vs[(mb + 2*t    )*132 + e];
                float x1 = Vs[(mb + 2*t + 1)*132 + e];
                hp[t] = b2pack(x0, x1);
                lp[t] = b2pack(x0 - bhi(x0), x1 - bhi(x1));
            }
            uint4* dh = reinterpret_cast<uint4*>(
                g_Vth + ((size_t)b*DOUT + e)*Mm + m0 + mb);
            uint4* dl = reinterpret_cast<uint4*>(
                g_Vtl + ((size_t)b*DOUT + e)*Mm + m0 + mb);
            #pragma unroll
            for (int q = 0; q < 4; q++) {
                dh[q] = make_uint4(hp[4*q],hp[4*q+1],hp[4*q+2],hp[4*q+3]);
                dl[q] = make_uint4(lp[4*q],lp[4*q+1],lp[4*q+2],lp[4*q+3]);
            }
        }
    }
}

// ---------------------------------------------------------------------------
// attnA: 512 threads, 16 warps (4m x 4n), warp tile 32x32,
// 128-key chunks, 2-stage ping-pong.
// smem: Qh+Ql 69632 | 2 x Kbuf (hi+lo) 69632 = 208896.
// ---------------------------------------------------------------------------
__global__ __launch_bounds__(512, 1)
void attnA_kernel(float* __restrict__ att)
{
    extern __shared__ char smraw[];
    const int tid = threadIdx.x, lane = tid & 31, wid = tid >> 5;
    const int b = blockIdx.y, m0 = blockIdx.x * 128;
    const int wm = wid >> 2, wn = wid & 3;

    char* Qh = smraw;
    char* Ql = smraw + 34816;
    char* Kb = smraw + 69632;            // 2 stages x 69632 (hi 34816 | lo 34816)
    const uint32_t sQh = cvta_smem(Qh), sQl = cvta_smem(Ql);
    const uint32_t sKb = cvta_smem(Kb);

    auto issueK = [&](int ch, int st) {
        const uint32_t dbase = sKb + st*69632;
        #pragma unroll
        for (int t = 0; t < 8; t++) {
            int i = tid + t*512;
            int tile = i >> 11, row = (i >> 4) & 127, p = i & 15;
            const __nv_bfloat16* src = (tile ? g_Kl : g_Kh)
                + ((size_t)(b*Mm + ch*128 + row))*DOUT + p*8;
            CPA(dbase + tile*34816 + row*PITB + p*16, src);
        }
        CPC();
    };

    issueK(0, 0);

    {
        const uint4* qh = reinterpret_cast<const uint4*>(g_Qh + ((size_t)b*Mm + m0)*DOUT);
        const uint4* ql = reinterpret_cast<const uint4*>(g_Ql + ((size_t)b*Mm + m0)*DOUT);
        for (int i = tid; i < 128*16; i += 512) {
            int row = i >> 4, c8 = i & 15;
            *reinterpret_cast<uint4*>(Qh + row*PITB + c8*16) = qh[i];
            *reinterpret_cast<uint4*>(Ql + row*PITB + c8*16) = ql[i];
        }
    }

    const int aRow  = wm*32 + (lane & 15);
    const int aKb   = (lane >> 4) * 8;
    const int bRow4 = wn*32 + ((lane >> 4) << 3) + (lane & 7);
    const int bK4   = ((lane >> 3) & 1) * 8;

    #pragma unroll 1
    for (int ch = 0; ch < 16; ch++) {
        int st = ch & 1;
        if (ch < 15) issueK(ch + 1, st ^ 1);
        if (ch < 15) { CPW1(); } else { CPW0(); }
        __syncthreads();

        const uint32_t kh = sKb + st*69632;
        const uint32_t kl = kh + 34816;

        float acc[2][4][4] = {};
        #pragma unroll
        for (int term = 0; term < 3; term++) {
            uint32_t sA = (term == 2) ? sQl : sQh;
            uint32_t sB = (term == 1) ? kl : kh;
            #pragma unroll
            for (int ks = 0; ks < 8; ks++) {
                uint32_t af[2][4];
                #pragma unroll
                for (int mi = 0; mi < 2; mi++)
                    ldmA(af[mi], sA + ((aRow + mi*16)*PIT + aKb + ks*16)*2);
                #pragma unroll
                for (int jj = 0; jj < 2; jj++) {
                    uint32_t bq4[4];
                    ldmB4(bq4, sB + (bRow4 + jj*16)*PITB + (bK4 + ks*16)*2);
                    #pragma unroll
                    for (int mi = 0; mi < 2; mi++) {
                        mma16816(acc[mi][2*jj],     af[mi], bq4);
                        mma16816(acc[mi][2*jj + 1], af[mi], bq4 + 2);
                    }
                }
            }
        }

        #pragma unroll
        for (int mi = 0; mi < 2; mi++)
            #pragma unroll
            for (int j = 0; j < 4; j++) {
                int r = wm*32 + mi*16 + (lane >> 2);
                int c = ch*128 + wn*32 + j*8 + (lane & 3)*2;
                *reinterpret_cast<float2*>(
                    att + ((size_t)(b*Mm + m0 + r))*Mm + c) =
                    make_float2(acc[mi][j][0], acc[mi][j][1]);
                *reinterpret_cast<float2*>(
                    att + ((size_t)(b*Mm + m0 + r + 8))*Mm + c) =
                    make_float2(acc[mi][j][2], acc[mi][j][3]);
            }
        __syncthreads();   // K stage fully consumed before its overwrite next iter
    }

    // softmax: warp wid owns rows [wid*8, wid*8+8); emits fp32 + bf16 split
    #pragma unroll 1
    for (int rr = 0; rr < 8; rr++) {
        size_t rowi = (size_t)(b*Mm + m0 + wid*8 + rr);
        float* row = att + rowi*Mm;
        float4 v[16];
        #pragma unroll
        for (int j = 0; j < 16; j++) v[j] = reinterpret_cast<float4*>(row)[lane + j*32];
        float mx = -1e30f;
        #pragma unroll
        for (int j = 0; j < 16; j++)
            mx = fmaxf(mx, fmaxf(fmaxf(v[j].x, v[j].y), fmaxf(v[j].z, v[j].w)));
        #pragma unroll
        for (int o = 16; o > 0; o >>= 1) mx = fmaxf(mx, __shfl_xor_sync(0xffffffffu, mx, o));
        float sum = 0.f;
        #pragma unroll
        for (int j = 0; j < 16; j++) {
            v[j].x = __expf(v[j].x - mx); v[j].y = __expf(v[j].y - mx);
            v[j].z = __expf(v[j].z - mx); v[j].w = __expf(v[j].w - mx);
            sum += (v[j].x + v[j].y) + (v[j].z + v[j].w);
        }
        #pragma unroll
        for (int o = 16; o > 0; o >>= 1) sum += __shfl_xor_sync(0xffffffffu, sum, o);
        float inv = 1.f / sum;
        uint2* ah = reinterpret_cast<uint2*>(g_Ah + rowi*Mm);
        uint2* al = reinterpret_cast<uint2*>(g_Al + rowi*Mm);
        #pragma unroll
        for (int j = 0; j < 16; j++) {
            v[j].x *= inv; v[j].y *= inv; v[j].z *= inv; v[j].w *= inv;
            reinterpret_cast<float4*>(row)[lane + j*32] = v[j];
            ah[lane + j*32] = make_uint2(b2pack(v[j].x, v[j].y), b2pack(v[j].z, v[j].w));
            al[lane + j*32] = make_uint2(
                b2pack(v[j].x - bhi(v[j].x), v[j].y - bhi(v[j].y)),
                b2pack(v[j].z - bhi(v[j].z), v[j].w - bhi(v[j].w)));
        }
    }
}

// ---------------------------------------------------------------------------
// attnC: 512 threads, 16 warps (4m x 4n), warp tile 32x32, 3-stage ring.
// smem: 3 x (Ah|Al|Bh|Bl each 18432) = 221184.
// ---------------------------------------------------------------------------
__global__ __launch_bounds__(512, 1)
void attnC_kernel(float* __restrict__ out)
{
    extern __shared__ char smraw[];
    const int tid = threadIdx.x, lane = tid & 31, wid = tid >> 5;
    const int b = blockIdx.y, m0 = blockIdx.x * 128;
    const int wm = wid >> 2, wn = wid & 3;

    const uint32_t sb = cvta_smem(smraw);

    auto issueC = [&](int ch, int st) {
        const uint32_t dbase = sb + st*73728;
        #pragma unroll
        for (int t = 0; t < 8; t++) {
            int i = tid + t*512;
            int tile = i >> 10, row = (i >> 3) & 127, p = i & 7;
            const __nv_bfloat16* src;
            if (tile == 0)
                src = g_Ah + ((size_t)(b*Mm + m0 + row))*Mm + ch*64 + p*8;
            else if (tile == 1)
                src = g_Al + ((size_t)(b*Mm + m0 + row))*Mm + ch*64 + p*8;
            else if (tile == 2)
                src = g_Vth + ((size_t)(b*DOUT + row))*Mm + ch*64 + p*8;
            else
                src = g_Vtl + ((size_t)(b*DOUT + row))*Mm + ch*64 + p*8;
            CPA(dbase + tile*18432 + row*P64B + p*16, src);
        }
        CPC();
    };

    issueC(0, 0);

    const int aRow  = wm*32 + (lane & 15);
    const int aKb   = (lane >> 4) * 8;
    const int bRow4 = wn*32 + ((lane >> 4) << 3) + (lane & 7);
    const int bK4   = ((lane >> 3) & 1) * 8;

    float acc[2][4][4] = {};

    int st = 0;
    #pragma unroll 1
    for (int ch = 0; ch < 32; ch++) {
        int nst = (st == 2) ? 0 : st + 1;
        if (ch < 31) issueC(ch + 1, nst);
        if (ch < 31) { CPW1(); } else { CPW0(); }
        __syncthreads();

        const uint32_t base = sb + st*73728;
        const uint32_t tAh = base, tAl = base + 18432;
        const uint32_t tBh = base + 36864, tBl = base + 55296;

        #pragma unroll
        for (int term = 0; term < 3; term++) {
            uint32_t sA = (term == 2) ? tAl : tAh;
            uint32_t sB = (term == 1) ? tBl : tBh;
            #pragma unroll
            for (int ks = 0; ks < 4; ks++) {
                uint32_t af[2][4];
                #pragma unroll
                for (int mi = 0; mi < 2; mi++)
                    ldmA(af[mi], sA + (aRow + mi*16)*P64B + (aKb + ks*16)*2);
                #pragma unroll
                for (int jj = 0; jj < 2; jj++) {
                    uint32_t bq4[4];
                    ldmB4(bq4, sB + (bRow4 + jj*16)*P64B + (bK4 + ks*16)*2);
                    #pragma unroll
                    for (int mi = 0; mi < 2; mi++) {
                        mma16816(acc[mi][2*jj],     af[mi], bq4);
                        mma16816(acc[mi][2*jj + 1], af[mi], bq4 + 2);
                    }
                }
            }
        }
        st = nst;
    }
    __syncthreads();   // all MMA done before Ss overwrites stage 0

    float* Ss = reinterpret_cast<float*>(smraw);
    #pragma unroll
    for (int mi = 0; mi < 2; mi++)
        #pragma unroll
        for (int j = 0; j < 4; j++) {
            int r = wm*32 + mi*16 + (lane >> 2);
            int c = wn*32 + j*8 + (lane & 3)*2;
            Ss[r*132 + c]         = acc[mi][j][0];
            Ss[r*132 + c + 1]     = acc[mi][j][1];
            Ss[(r+8)*132 + c]     = acc[mi][j][2];
            Ss[(r+8)*132 + c + 1] = acc[mi][j][3];
        }
    __syncthreads();

    #pragma unroll 1
    for (int rr = 0; rr < 8; rr++) {
        int r = wid*8 + rr;
        float a0 = Ss[r*132 + lane],      a1 = Ss[r*132 + lane + 32];
        float a2 = Ss[r*132 + lane + 64], a3 = Ss[r*132 + lane + 96];
        float ss = a0*a0 + a1*a1 + a2*a2 + a3*a3;
        #pragma unroll
        for (int o = 16; o > 0; o >>= 1) ss += __shfl_xor_sync(0xffffffffu, ss, o);
        float inv1 = rsqrtf(fmaxf(ss, 1e-12f));
        const float* vrow = g_V + ((size_t)b*Mm + m0 + r)*DOUT;
        float t0 = vrow[lane]      + a0*inv1;
        float t1 = vrow[lane + 32] + a1*inv1;
        float t2 = vrow[lane + 64] + a2*inv1;
        float t3 = vrow[lane + 96] + a3*inv1;
        float ss2 = t0*t0 + t1*t1 + t2*t2 + t3*t3;
        #pragma unroll
        for (int o = 16; o > 0; o >>= 1) ss2 += __shfl_xor_sync(0xffffffffu, ss2, o);
        float inv2 = rsqrtf(fmaxf(ss2, 1e-12f));
        float* orow = out + ((size_t)b*Mm + m0 + r)*DOUT;
        orow[lane]      = t0*inv2;
        orow[lane + 32] = t1*inv2;
        orow[lane + 64] = t2*inv2;
        orow[lane + 96] = t3*inv2;
    }
}

// ---------------------------------------------------------------------------
extern "C" void kernel_launch(void* const* d_in, const int* in_sizes, int n_in,
                              void* d_out, int out_size)
{
    const float* Y   = (const float*)d_in[0];
    const int*   idx = (const int*)  d_in[1];
    const float* Wq  = (const float*)d_in[2];
    const float* bq  = (const float*)d_in[3];
    const float* Wk  = (const float*)d_in[4];
    const float* bk  = (const float*)d_in[5];
    const float* Wv  = (const float*)d_in[6];
    const float* bv  = (const float*)d_in[7];

    float* out = (float*)d_out;                       // [8,2048,128]
    float* att = out + (size_t)Bb*Mm*DOUT;            // [8,2048,2048]

    const int smemP = 208896;
    const int smemA = 208896;
    const int smemC = 221184;

    cudaFuncSetAttribute(projmma_kernel, cudaFuncAttributeMaxDynamicSharedMemorySize, smemP);
    cudaFuncSetAttribute(attnA_kernel,   cudaFuncAttributeMaxDynamicSharedMemorySize, smemA);
    cudaFuncSetAttribute(attnC_kernel,   cudaFuncAttributeMaxDynamicSharedMemorySize, smemC);

    prep_kernel<<<3, 256>>>(Wq, Wk, Wv);
    projmma_kernel<<<(Bb*Mm)/128, 512, smemP>>>(Y, idx, bq, bk, bv);
    attnA_kernel<<<dim3(Mm/128, Bb), 512, smemA>>>(att);
    attnC_kernel<<<dim3(Mm/128, Bb), 512, smemC>>>(out);
}

// round 11
// speedup vs baseline: 1.1408x; 1.1408x over previous
#include <cuda_runtime.h>
#include <cuda_bf16.h>
#include <cstdint>

#define Bb   8
#define Nn   4096
#define Mm   2048
#define DIN  256
#define DOUT 128

__device__ __nv_bfloat16 g_Qh [Bb*Mm*DOUT];
__device__ __nv_bfloat16 g_Ql [Bb*Mm*DOUT];
__device__ __nv_bfloat16 g_Kh [Bb*Mm*DOUT];
__device__ __nv_bfloat16 g_Kl [Bb*Mm*DOUT];
__device__ float         g_V  [Bb*Mm*DOUT];
__device__ __nv_bfloat16 g_Vth[Bb*DOUT*Mm];    // [b][e][m]
__device__ __nv_bfloat16 g_Vtl[Bb*DOUT*Mm];
__device__ __nv_bfloat16 g_Wth[3*DOUT*DIN];    // [wsel][n][k]
__device__ __nv_bfloat16 g_Wtl[3*DOUT*DIN];
__device__ __nv_bfloat16 g_Ah [(size_t)Bb*Mm*Mm];
__device__ __nv_bfloat16 g_Al [(size_t)Bb*Mm*Mm];

// ---------------- helpers ----------------
__device__ __forceinline__ uint32_t cvta_smem(const void* p) {
    uint32_t a;
    asm("{ .reg .u64 t; cvta.to.shared.u64 t, %1; cvt.u32.u64 %0, t; }" : "=r"(a) : "l"(p));
    return a;
}
__device__ __forceinline__ uint32_t b2pack(float a, float b) {
    uint16_t la = __bfloat16_as_ushort(__float2bfloat16(a));
    uint16_t lb = __bfloat16_as_ushort(__float2bfloat16(b));
    return (uint32_t)la | ((uint32_t)lb << 16);
}
__device__ __forceinline__ float bhi(float x) {
    return __bfloat162float(__float2bfloat16(x));
}
__device__ __forceinline__ void ldmA(uint32_t a[4], uint32_t addr) {
    asm volatile("ldmatrix.sync.aligned.m8n8.x4.shared.b16 {%0,%1,%2,%3}, [%4];"
        : "=r"(a[0]),"=r"(a[1]),"=r"(a[2]),"=r"(a[3]) : "r"(addr));
}
__device__ __forceinline__ void ldmB4(uint32_t b[4], uint32_t addr) {
    asm volatile("ldmatrix.sync.aligned.m8n8.x4.shared.b16 {%0,%1,%2,%3}, [%4];"
        : "=r"(b[0]),"=r"(b[1]),"=r"(b[2]),"=r"(b[3]) : "r"(addr));
}
__device__ __forceinline__ void mma16816(float c[4], const uint32_t a[4], const uint32_t b[2]) {
    asm volatile("mma.sync.aligned.m16n8k16.row.col.f32.bf16.bf16.f32 "
        "{%0,%1,%2,%3}, {%4,%5,%6,%7}, {%8,%9}, {%0,%1,%2,%3};"
        : "+f"(c[0]),"+f"(c[1]),"+f"(c[2]),"+f"(c[3])
        : "r"(a[0]),"r"(a[1]),"r"(a[2]),"r"(a[3]), "r"(b[0]),"r"(b[1]));
}
#define CPA(d, s) asm volatile("cp.async.cg.shared.global [%0], [%1], 16;" :: "r"(d), "l"(s))
#define CPC()     asm volatile("cp.async.commit_group;" ::: "memory")
#define CPW1()    asm volatile("cp.async.wait_group 1;" ::: "memory")
#define CPW0()    asm volatile("cp.async.wait_group 0;" ::: "memory")

#define PIT 136
#define PITB 272
#define P64B 144

// ---------------------------------------------------------------------------
__global__ void prep_kernel(const float* __restrict__ Wq,
                            const float* __restrict__ Wk,
                            const float* __restrict__ Wv)
{
    const float* W = (blockIdx.x == 0) ? Wq : (blockIdx.x == 1) ? Wk : Wv;
    __nv_bfloat16* dh = g_Wth + blockIdx.x * DOUT * DIN;
    __nv_bfloat16* dl = g_Wtl + blockIdx.x * DOUT * DIN;
    for (int i = threadIdx.x; i < DOUT * (DIN/2); i += 256) {
        int n = i >> 7, k = (i & 127) * 2;
        float x0 = W[(size_t)k*DOUT + n];
        float x1 = W[(size_t)(k+1)*DOUT + n];
        *reinterpret_cast<uint32_t*>(dh + (size_t)n*DIN + k) = b2pack(x0, x1);
        *reinterpret_cast<uint32_t*>(dl + (size_t)n*DIN + k) =
            b2pack(x0 - bhi(x0), x1 - bhi(x1));
    }
}

// ---------------------------------------------------------------------------
// projmma (round-9 best): 256 threads, 8 warps (4m x 2n), warp tile 32x64.
// ---------------------------------------------------------------------------
__global__ __launch_bounds__(256, 1)
void projmma_kernel(const float* __restrict__ Y, const int* __restrict__ idx,
                    const float* __restrict__ bq, const float* __restrict__ bk,
                    const float* __restrict__ bv)
{
    extern __shared__ char smraw[];
    char* Ah = smraw;                    // 2 k-chunks x 34816
    char* Al = smraw + 69632;
    char* Bh = smraw + 139264;
    char* Bl = smraw + 174080;
    float* Vs = reinterpret_cast<float*>(Bh);
    __shared__ int idxs[128];

    const int tid = threadIdx.x, lane = tid & 31, wid = tid >> 5;
    const int wm = wid >> 1, wn = wid & 1;
    const int row0 = blockIdx.x * 128;
    const int b    = row0 / Mm;
    const int m0   = row0 % Mm;

    if (tid < 128) idxs[tid] = idx[b*Mm + m0 + tid];
    __syncthreads();

    for (int i = tid; i < 128*64; i += 256) {
        int row = i >> 6, c4 = i & 63;
        float4 y = *reinterpret_cast<const float4*>(
            Y + ((size_t)b*Nn + idxs[row])*DIN + c4*4);
        int kc = c4 >> 5;
        uint32_t off = (uint32_t)(kc*34816 + row*PITB + (c4 & 31)*8);
        *reinterpret_cast<uint2*>(Ah + off) =
            make_uint2(b2pack(y.x, y.y), b2pack(y.z, y.w));
        *reinterpret_cast<uint2*>(Al + off) =
            make_uint2(b2pack(y.x-bhi(y.x), y.y-bhi(y.y)),
                       b2pack(y.z-bhi(y.z), y.w-bhi(y.w)));
    }

    const uint32_t sAh = cvta_smem(Ah), sAl = cvta_smem(Al);
    const uint32_t sBh = cvta_smem(Bh), sBl = cvta_smem(Bl);

    const int aRow  = wm*32 + (lane & 15);
    const int aKb   = (lane >> 4) * 8;
    const int bRow4 = wn*64 + ((lane >> 4) << 3) + (lane & 7);
    const int bK4   = ((lane >> 3) & 1) * 8;

    #pragma unroll 1
    for (int wsel = 0; wsel < 3; wsel++) {
        float acc[2][8][4] = {};
        #pragma unroll 1
        for (int kc = 0; kc < 2; kc++) {
            __syncthreads();
            const __nv_bfloat16* wh = g_Wth + (size_t)wsel*DOUT*DIN + kc*128;
            const __nv_bfloat16* wl = g_Wtl + (size_t)wsel*DOUT*DIN + kc*128;
            for (int i = tid; i < 128*16; i += 256) {
                int n = i >> 4, c8 = i & 15;
                uint32_t off = (uint32_t)(n*PITB + c8*16);
                size_t go = (size_t)n*DIN + c8*8;
                *reinterpret_cast<uint4*>(Bh + off) =
                    *reinterpret_cast<const uint4*>(wh + go);
                *reinterpret_cast<uint4*>(Bl + off) =
                    *reinterpret_cast<const uint4*>(wl + go);
            }
            __syncthreads();
            uint32_t aBase = kc * 34816;
            #pragma unroll
            for (int term = 0; term < 3; term++) {
                uint32_t sA = ((term == 2) ? sAl : sAh) + aBase;
                uint32_t sB = (term == 1) ? sBl : sBh;
                #pragma unroll
                for (int ks = 0; ks < 8; ks++) {
                    uint32_t af[2][4];
                    #pragma unroll
                    for (int mi = 0; mi < 2; mi++)
                        ldmA(af[mi], sA + ((aRow + mi*16)*PIT + aKb + ks*16)*2);
                    #pragma unroll
                    for (int jj = 0; jj < 4; jj++) {
                        uint32_t bq4[4];
                        ldmB4(bq4, sB + ((bRow4 + jj*16)*PIT + bK4 + ks*16)*2);
                        #pragma unroll
                        for (int mi = 0; mi < 2; mi++) {
                            mma16816(acc[mi][2*jj],     af[mi], bq4);
                            mma16816(acc[mi][2*jj + 1], af[mi], bq4 + 2);
                        }
                    }
                }
            }
        }

        const float* bp = (wsel == 0) ? bq : (wsel == 1) ? bk : bv;
        float bias2[8][2];
        #pragma unroll
        for (int j = 0; j < 8; j++) {
            int c = wn*64 + j*8 + (lane & 3)*2;
            bias2[j][0] = bp[c]; bias2[j][1] = bp[c+1];
        }

        if (wsel < 2) {
            const float s = (wsel == 0) ? 0.0625f : 1.0f;
            __nv_bfloat16* gh = (wsel == 0) ? g_Qh : g_Kh;
            __nv_bfloat16* gl = (wsel == 0) ? g_Ql : g_Kl;
            #pragma unroll
            for (int mi = 0; mi < 2; mi++)
                #pragma unroll
                for (int j = 0; j < 8; j++) {
                    int r = wm*32 + mi*16 + (lane >> 2);
                    int c = wn*64 + j*8 + (lane & 3)*2;
                    float q0 = (acc[mi][j][0] + bias2[j][0]) * s;
                    float q1 = (acc[mi][j][1] + bias2[j][1]) * s;
                    float q2 = (acc[mi][j][2] + bias2[j][0]) * s;
                    float q3 = (acc[mi][j][3] + bias2[j][1]) * s;
                    size_t o0 = ((size_t)(b*Mm + m0 + r))*DOUT + c;
                    size_t o1 = ((size_t)(b*Mm + m0 + r + 8))*DOUT + c;
                    *reinterpret_cast<uint32_t*>(gh + o0) = b2pack(q0, q1);
                    *reinterpret_cast<uint32_t*>(gl + o0) =
                        b2pack(q0 - bhi(q0), q1 - bhi(q1));
                    *reinterpret_cast<uint32_t*>(gh + o1) = b2pack(q2, q3);
                    *reinterpret_cast<uint32_t*>(gl + o1) =
                        b2pack(q2 - bhi(q2), q3 - bhi(q3));
                }
        } else {
            __syncthreads();
            #pragma unroll
            for (int mi = 0; mi < 2; mi++)
                #pragma unroll
                for (int j = 0; j < 8; j++) {
                    int r = wm*32 + mi*16 + (lane >> 2);
                    int c = wn*64 + j*8 + (lane & 3)*2;
                    float v0 = fmaxf(acc[mi][j][0] + bias2[j][0], 0.f);
                    float v1 = fmaxf(acc[mi][j][1] + bias2[j][1], 0.f);
                    float v2 = fmaxf(acc[mi][j][2] + bias2[j][0], 0.f);
                    float v3 = fmaxf(acc[mi][j][3] + bias2[j][1], 0.f);
                    *reinterpret_cast<float2*>(
                        g_V + ((size_t)(b*Mm + m0 + r))*DOUT + c) = make_float2(v0, v1);
                    *reinterpret_cast<float2*>(
                        g_V + ((size_t)(b*Mm + m0 + r + 8))*DOUT + c) = make_float2(v2, v3);
                    Vs[r*132 + c]       = v0;
                    Vs[r*132 + c + 1]   = v1;
                    Vs[(r+8)*132 + c]   = v2;
                    Vs[(r+8)*132 + c+1] = v3;
                }
            __syncthreads();
            int e = tid & 127, half = tid >> 7;
            #pragma unroll
            for (int seg = 0; seg < 2; seg++) {
                int mb = half*64 + seg*32;
                uint32_t hp[16], lp[16];
                #pragma unroll
                for (int t = 0; t < 16; t++) {
                    float x0 = Vs[(mb + 2*t    )*132 + e];
                    float x1 = Vs[(mb + 2*t + 1)*132 + e];
                    hp[t] = b2pack(x0, x1);
                    lp[t] = b2pack(x0 - bhi(x0), x1 - bhi(x1));
                }
                uint4* dh = reinterpret_cast<uint4*>(
                    g_Vth + ((size_t)b*DOUT + e)*Mm + m0 + mb);
                uint4* dl = reinterpret_cast<uint4*>(
                    g_Vtl + ((size_t)b*DOUT + e)*Mm + m0 + mb);
                #pragma unroll
                for (int q = 0; q < 4; q++) {
                    dh[q] = make_uint4(hp[4*q],hp[4*q+1],hp[4*q+2],hp[4*q+3]);
                    dl[q] = make_uint4(lp[4*q],lp[4*q+1],lp[4*q+2],lp[4*q+3]);
                }
            }
        }
    }
}

// ---------------------------------------------------------------------------
// attnA (round-9 best): 256 threads, 8 warps (4m x 2n), warp tile 32x32,
// 3-stage ring. smem: Qh 34816 | Ql 34816 | 3 x Kbuf 34816 = 174080.
// ---------------------------------------------------------------------------
__global__ __launch_bounds__(256, 1)
void attnA_kernel(float* __restrict__ att)
{
    extern __shared__ char smraw[];
    const int tid = threadIdx.x, lane = tid & 31, wid = tid >> 5;
    const int b = blockIdx.y, m0 = blockIdx.x * 128;
    const int wm = wid >> 1, wn = wid & 1;

    char* Qh = smraw;
    char* Ql = smraw + 34816;
    char* Kb = smraw + 69632;
    const uint32_t sQh = cvta_smem(Qh), sQl = cvta_smem(Ql);
    const uint32_t sKb = cvta_smem(Kb);

    auto issueK = [&](int ch, int st) {
        const uint32_t dbase = sKb + st*34816;
        #pragma unroll
        for (int t = 0; t < 8; t++) {
            int i = tid + t*256;
            int tile = i >> 10, row = (i >> 4) & 63, p = i & 15;
            const __nv_bfloat16* src = (tile ? g_Kl : g_Kh)
                + ((size_t)(b*Mm + ch*64 + row))*DOUT + p*8;
            CPA(dbase + tile*17408 + row*PITB + p*16, src);
        }
        CPC();
    };

    issueK(0, 0);

    {
        const uint4* qh = reinterpret_cast<const uint4*>(g_Qh + ((size_t)b*Mm + m0)*DOUT);
        const uint4* ql = reinterpret_cast<const uint4*>(g_Ql + ((size_t)b*Mm + m0)*DOUT);
        for (int i = tid; i < 128*16; i += 256) {
            int row = i >> 4, c8 = i & 15;
            *reinterpret_cast<uint4*>(Qh + row*PITB + c8*16) = qh[i];
            *reinterpret_cast<uint4*>(Ql + row*PITB + c8*16) = ql[i];
        }
    }

    const int aRow  = wm*32 + (lane & 15);
    const int aKb   = (lane >> 4) * 8;
    const int bRow4 = wn*32 + ((lane >> 4) << 3) + (lane & 7);
    const int bK4   = ((lane >> 3) & 1) * 8;

    int st = 0;
    #pragma unroll 1
    for (int ch = 0; ch < 32; ch++) {
        int nst = (st == 2) ? 0 : st + 1;
        if (ch < 31) issueK(ch + 1, nst);
        if (ch < 31) { CPW1(); } else { CPW0(); }
        __syncthreads();

        const uint32_t kh = sKb + st*34816;
        const uint32_t kl = kh + 17408;

        float acc[2][4][4] = {};
        #pragma unroll
        for (int term = 0; term < 3; term++) {
            uint32_t sA = (term == 2) ? sQl : sQh;
            uint32_t sB = (term == 1) ? kl : kh;
            #pragma unroll
            for (int ks = 0; ks < 8; ks++) {
                uint32_t af[2][4];
                #pragma unroll
                for (int mi = 0; mi < 2; mi++)
                    ldmA(af[mi], sA + ((aRow + mi*16)*PIT + aKb + ks*16)*2);
                #pragma unroll
                for (int jj = 0; jj < 2; jj++) {
                    uint32_t bq4[4];
                    ldmB4(bq4, sB + (bRow4 + jj*16)*PITB + (bK4 + ks*16)*2);
                    #pragma unroll
                    for (int mi = 0; mi < 2; mi++) {
                        mma16816(acc[mi][2*jj],     af[mi], bq4);
                        mma16816(acc[mi][2*jj + 1], af[mi], bq4 + 2);
                    }
                }
            }
        }

        #pragma unroll
        for (int mi = 0; mi < 2; mi++)
            #pragma unroll
            for (int j = 0; j < 4; j++) {
                int r = wm*32 + mi*16 + (lane >> 2);
                int c = ch*64 + wn*32 + j*8 + (lane & 3)*2;
                *reinterpret_cast<float2*>(
                    att + ((size_t)(b*Mm + m0 + r))*Mm + c) =
                    make_float2(acc[mi][j][0], acc[mi][j][1]);
                *reinterpret_cast<float2*>(
                    att + ((size_t)(b*Mm + m0 + r + 8))*Mm + c) =
                    make_float2(acc[mi][j][2], acc[mi][j][3]);
            }
        st = nst;
    }
    __syncthreads();

    // softmax: warp wid owns rows [wid*16, wid*16+16); emits fp32 + bf16 split
    #pragma unroll 1
    for (int rr = 0; rr < 16; rr++) {
        size_t rowi = (size_t)(b*Mm + m0 + wid*16 + rr);
        float* row = att + rowi*Mm;
        float4 v[16];
        #pragma unroll
        for (int j = 0; j < 16; j++) v[j] = reinterpret_cast<float4*>(row)[lane + j*32];
        float mx = -1e30f;
        #pragma unroll
        for (int j = 0; j < 16; j++)
            mx = fmaxf(mx, fmaxf(fmaxf(v[j].x, v[j].y), fmaxf(v[j].z, v[j].w)));
        #pragma unroll
        for (int o = 16; o > 0; o >>= 1) mx = fmaxf(mx, __shfl_xor_sync(0xffffffffu, mx, o));
        float sum = 0.f;
        #pragma unroll
        for (int j = 0; j < 16; j++) {
            v[j].x = __expf(v[j].x - mx); v[j].y = __expf(v[j].y - mx);
            v[j].z = __expf(v[j].z - mx); v[j].w = __expf(v[j].w - mx);
            sum += (v[j].x + v[j].y) + (v[j].z + v[j].w);
        }
        #pragma unroll
        for (int o = 16; o > 0; o >>= 1) sum += __shfl_xor_sync(0xffffffffu, sum, o);
        float inv = 1.f / sum;
        uint2* ah = reinterpret_cast<uint2*>(g_Ah + rowi*Mm);
        uint2* al = reinterpret_cast<uint2*>(g_Al + rowi*Mm);
        #pragma unroll
        for (int j = 0; j < 16; j++) {
            v[j].x *= inv; v[j].y *= inv; v[j].z *= inv; v[j].w *= inv;
            reinterpret_cast<float4*>(row)[lane + j*32] = v[j];
            ah[lane + j*32] = make_uint2(b2pack(v[j].x, v[j].y), b2pack(v[j].z, v[j].w));
            al[lane + j*32] = make_uint2(
                b2pack(v[j].x - bhi(v[j].x), v[j].y - bhi(v[j].y)),
                b2pack(v[j].z - bhi(v[j].z), v[j].w - bhi(v[j].w)));
        }
    }
}

// ---------------------------------------------------------------------------
// attnC (round-10 best): 512 threads, 16 warps (4m x 4n), warp tile 32x32,
// 3-stage ring. smem: 3 x (Ah|Al|Bh|Bl each 18432) = 221184.
// ---------------------------------------------------------------------------
__global__ __launch_bounds__(512, 1)
void attnC_kernel(float* __restrict__ out)
{
    extern __shared__ char smraw[];
    const int tid = threadIdx.x, lane = tid & 31, wid = tid >> 5;
    const int b = blockIdx.y, m0 = blockIdx.x * 128;
    const int wm = wid >> 2, wn = wid & 3;

    const uint32_t sb = cvta_smem(smraw);

    auto issueC = [&](int ch, int st) {
        const uint32_t dbase = sb + st*73728;
        #pragma unroll
        for (int t = 0; t < 8; t++) {
            int i = tid + t*512;
            int tile = i >> 10, row = (i >> 3) & 127, p = i & 7;
            const __nv_bfloat16* src;
            if (tile == 0)
                src = g_Ah + ((size_t)(b*Mm + m0 + row))*Mm + ch*64 + p*8;
            else if (tile == 1)
                src = g_Al + ((size_t)(b*Mm + m0 + row))*Mm + ch*64 + p*8;
            else if (tile == 2)
                src = g_Vth + ((size_t)(b*DOUT + row))*Mm + ch*64 + p*8;
            else
                src = g_Vtl + ((size_t)(b*DOUT + row))*Mm + ch*64 + p*8;
            CPA(dbase + tile*18432 + row*P64B + p*16, src);
        }
        CPC();
    };

    issueC(0, 0);

    const int aRow  = wm*32 + (lane & 15);
    const int aKb   = (lane >> 4) * 8;
    const int bRow4 = wn*32 + ((lane >> 4) << 3) + (lane & 7);
    const int bK4   = ((lane >> 3) & 1) * 8;

    float acc[2][4][4] = {};

    int st = 0;
    #pragma unroll 1
    for (int ch = 0; ch < 32; ch++) {
        int nst = (st == 2) ? 0 : st + 1;
        if (ch < 31) issueC(ch + 1, nst);
        if (ch < 31) { CPW1(); } else { CPW0(); }
        __syncthreads();

        const uint32_t base = sb + st*73728;
        const uint32_t tAh = base, tAl = base + 18432;
        const uint32_t tBh = base + 36864, tBl = base + 55296;

        #pragma unroll
        for (int term = 0; term < 3; term++) {
            uint32_t sA = (term == 2) ? tAl : tAh;
            uint32_t sB = (term == 1) ? tBl : tBh;
            #pragma unroll
            for (int ks = 0; ks < 4; ks++) {
                uint32_t af[2][4];
                #pragma unroll
                for (int mi = 0; mi < 2; mi++)
                    ldmA(af[mi], sA + (aRow + mi*16)*P64B + (aKb + ks*16)*2);
                #pragma unroll
                for (int jj = 0; jj < 2; jj++) {
                    uint32_t bq4[4];
                    ldmB4(bq4, sB + (bRow4 + jj*16)*P64B + (bK4 + ks*16)*2);
                    #pragma unroll
                    for (int mi = 0; mi < 2; mi++) {
                        mma16816(acc[mi][2*jj],     af[mi], bq4);
                        mma16816(acc[mi][2*jj + 1], af[mi], bq4 + 2);
                    }
                }
            }
        }
        st = nst;
    }
    __syncthreads();   // all MMA done before Ss overwrites stage 0

    float* Ss = reinterpret_cast<float*>(smraw);
    #pragma unroll
    for (int mi = 0; mi < 2; mi++)
        #pragma unroll
        for (int j = 0; j < 4; j++) {
            int r = wm*32 + mi*16 + (lane >> 2);
            int c = wn*32 + j*8 + (lane & 3)*2;
            Ss[r*132 + c]         = acc[mi][j][0];
            Ss[r*132 + c + 1]     = acc[mi][j][1];
            Ss[(r+8)*132 + c]     = acc[mi][j][2];
            Ss[(r+8)*132 + c + 1] = acc[mi][j][3];
        }
    __syncthreads();

    #pragma unroll 1
    for (int rr = 0; rr < 8; rr++) {
        int r = wid*8 + rr;
        float a0 = Ss[r*132 + lane],      a1 = Ss[r*132 + lane + 32];
        float a2 = Ss[r*132 + lane + 64], a3 = Ss[r*132 + lane + 96];
        float ss = a0*a0 + a1*a1 + a2*a2 + a3*a3;
        #pragma unroll
        for (int o = 16; o > 0; o >>= 1) ss += __shfl_xor_sync(0xffffffffu, ss, o);
        float inv1 = rsqrtf(fmaxf(ss, 1e-12f));
        const float* vrow = g_V + ((size_t)b*Mm + m0 + r)*DOUT;
        float t0 = vrow[lane]      + a0*inv1;
        float t1 = vrow[lane + 32] + a1*inv1;
        float t2 = vrow[lane + 64] + a2*inv1;
        float t3 = vrow[lane + 96] + a3*inv1;
        float ss2 = t0*t0 + t1*t1 + t2*t2 + t3*t3;
        #pragma unroll
        for (int o = 16; o > 0; o >>= 1) ss2 += __shfl_xor_sync(0xffffffffu, ss2, o);
        float inv2 = rsqrtf(fmaxf(ss2, 1e-12f));
        float* orow = out + ((size_t)b*Mm + m0 + r)*DOUT;
        orow[lane]      = t0*inv2;
        orow[lane + 32] = t1*inv2;
        orow[lane + 64] = t2*inv2;
        orow[lane + 96] = t3*inv2;
    }
}

// ---------------------------------------------------------------------------
extern "C" void kernel_launch(void* const* d_in, const int* in_sizes, int n_in,
                              void* d_out, int out_size)
{
    const float* Y   = (const float*)d_in[0];
    const int*   idx = (const int*)  d_in[1];
    const float* Wq  = (const float*)d_in[2];
    const float* bq  = (const float*)d_in[3];
    const float* Wk  = (const float*)d_in[4];
    const float* bk  = (const float*)d_in[5];
    const float* Wv  = (const float*)d_in[6];
    const float* bv  = (const float*)d_in[7];

    float* out = (float*)d_out;                       // [8,2048,128]
    float* att = out + (size_t)Bb*Mm*DOUT;            // [8,2048,2048]

    const int smemP = 208896;
    const int smemA = 174080;
    const int smemC = 221184;

    cudaFuncSetAttribute(projmma_kernel, cudaFuncAttributeMaxDynamicSharedMemorySize, smemP);
    cudaFuncSetAttribute(attnA_kernel,   cudaFuncAttributeMaxDynamicSharedMemorySize, smemA);
    cudaFuncSetAttribute(attnC_kernel,   cudaFuncAttributeMaxDynamicSharedMemorySize, smemC);

    prep_kernel<<<3, 256>>>(Wq, Wk, Wv);
    projmma_kernel<<<(Bb*Mm)/128, 256, smemP>>>(Y, idx, bq, bk, bv);
    attnA_kernel<<<dim3(Mm/128, Bb), 256, smemA>>>(att);
    attnC_kernel<<<dim3(Mm/128, Bb), 512, smemC>>>(out);
}

// round 12
// speedup vs baseline: 1.2416x; 1.0883x over previous
#include <cuda_runtime.h>
#include <cuda_bf16.h>
#include <cstdint>

#define Bb   8
#define Nn   4096
#define Mm   2048
#define DIN  256
#define DOUT 128

__device__ __nv_bfloat16 g_Qh [Bb*Mm*DOUT];
__device__ __nv_bfloat16 g_Ql [Bb*Mm*DOUT];
__device__ __nv_bfloat16 g_Kh [Bb*Mm*DOUT];
__device__ __nv_bfloat16 g_Kl [Bb*Mm*DOUT];
__device__ float         g_V  [Bb*Mm*DOUT];
__device__ __nv_bfloat16 g_Vth[Bb*DOUT*Mm];    // [b][e][m]
__device__ __nv_bfloat16 g_Vtl[Bb*DOUT*Mm];
__device__ __nv_bfloat16 g_Wth[3*DOUT*DIN];    // [wsel][n][k]
__device__ __nv_bfloat16 g_Wtl[3*DOUT*DIN];

// ---------------- helpers ----------------
__device__ __forceinline__ uint32_t cvta_smem(const void* p) {
    uint32_t a;
    asm("{ .reg .u64 t; cvta.to.shared.u64 t, %1; cvt.u32.u64 %0, t; }" : "=r"(a) : "l"(p));
    return a;
}
__device__ __forceinline__ uint32_t b2pack(float a, float b) {
    uint16_t la = __bfloat16_as_ushort(__float2bfloat16(a));
    uint16_t lb = __bfloat16_as_ushort(__float2bfloat16(b));
    return (uint32_t)la | ((uint32_t)lb << 16);
}
__device__ __forceinline__ float bhi(float x) {
    return __bfloat162float(__float2bfloat16(x));
}
__device__ __forceinline__ void ldmA(uint32_t a[4], uint32_t addr) {
    asm volatile("ldmatrix.sync.aligned.m8n8.x4.shared.b16 {%0,%1,%2,%3}, [%4];"
        : "=r"(a[0]),"=r"(a[1]),"=r"(a[2]),"=r"(a[3]) : "r"(addr));
}
__device__ __forceinline__ void ldmB4(uint32_t b[4], uint32_t addr) {
    asm volatile("ldmatrix.sync.aligned.m8n8.x4.shared.b16 {%0,%1,%2,%3}, [%4];"
        : "=r"(b[0]),"=r"(b[1]),"=r"(b[2]),"=r"(b[3]) : "r"(addr));
}
__device__ __forceinline__ void mma16816(float c[4], const uint32_t a[4], const uint32_t b[2]) {
    asm volatile("mma.sync.aligned.m16n8k16.row.col.f32.bf16.bf16.f32 "
        "{%0,%1,%2,%3}, {%4,%5,%6,%7}, {%8,%9}, {%0,%1,%2,%3};"
        : "+f"(c[0]),"+f"(c[1]),"+f"(c[2]),"+f"(c[3])
        : "r"(a[0]),"r"(a[1]),"r"(a[2]),"r"(a[3]), "r"(b[0]),"r"(b[1]));
}
#define CPA(d, s) asm volatile("cp.async.cg.shared.global [%0], [%1], 16;" :: "r"(d), "l"(s))
#define CPC()     asm volatile("cp.async.commit_group;" ::: "memory")
#define CPW1()    asm volatile("cp.async.wait_group 1;" ::: "memory")
#define CPW0()    asm volatile("cp.async.wait_group 0;" ::: "memory")

#define PIT 136
#define PITB 272
#define P64B 144

// ---------------------------------------------------------------------------
__global__ void prep_kernel(const float* __restrict__ Wq,
                            const float* __restrict__ Wk,
                            const float* __restrict__ Wv)
{
    const float* W = (blockIdx.x == 0) ? Wq : (blockIdx.x == 1) ? Wk : Wv;
    __nv_bfloat16* dh = g_Wth + blockIdx.x * DOUT * DIN;
    __nv_bfloat16* dl = g_Wtl + blockIdx.x * DOUT * DIN;
    for (int i = threadIdx.x; i < DOUT * (DIN/2); i += 256) {
        int n = i >> 7, k = (i & 127) * 2;
        float x0 = W[(size_t)k*DOUT + n];
        float x1 = W[(size_t)(k+1)*DOUT + n];
        *reinterpret_cast<uint32_t*>(dh + (size_t)n*DIN + k) = b2pack(x0, x1);
        *reinterpret_cast<uint32_t*>(dl + (size_t)n*DIN + k) =
            b2pack(x0 - bhi(x0), x1 - bhi(x1));
    }
}

// ---------------------------------------------------------------------------
// projmma (round-9 proven): 256 threads, 8 warps (4m x 2n), warp tile 32x64.
// ---------------------------------------------------------------------------
__global__ __launch_bounds__(256, 1)
void projmma_kernel(const float* __restrict__ Y, const int* __restrict__ idx,
                    const float* __restrict__ bq, const float* __restrict__ bk,
                    const float* __restrict__ bv)
{
    extern __shared__ char smraw[];
    char* Ah = smraw;                    // 2 k-chunks x 34816
    char* Al = smraw + 69632;
    char* Bh = smraw + 139264;
    char* Bl = smraw + 174080;
    float* Vs = reinterpret_cast<float*>(Bh);
    __shared__ int idxs[128];

    const int tid = threadIdx.x, lane = tid & 31, wid = tid >> 5;
    const int wm = wid >> 1, wn = wid & 1;
    const int row0 = blockIdx.x * 128;
    const int b    = row0 / Mm;
    const int m0   = row0 % Mm;

    if (tid < 128) idxs[tid] = idx[b*Mm + m0 + tid];
    __syncthreads();

    for (int i = tid; i < 128*64; i += 256) {
        int row = i >> 6, c4 = i & 63;
        float4 y = *reinterpret_cast<const float4*>(
            Y + ((size_t)b*Nn + idxs[row])*DIN + c4*4);
        int kc = c4 >> 5;
        uint32_t off = (uint32_t)(kc*34816 + row*PITB + (c4 & 31)*8);
        *reinterpret_cast<uint2*>(Ah + off) =
            make_uint2(b2pack(y.x, y.y), b2pack(y.z, y.w));
        *reinterpret_cast<uint2*>(Al + off) =
            make_uint2(b2pack(y.x-bhi(y.x), y.y-bhi(y.y)),
                       b2pack(y.z-bhi(y.z), y.w-bhi(y.w)));
    }

    const uint32_t sAh = cvta_smem(Ah), sAl = cvta_smem(Al);
    const uint32_t sBh = cvta_smem(Bh), sBl = cvta_smem(Bl);

    const int aRow  = wm*32 + (lane & 15);
    const int aKb   = (lane >> 4) * 8;
    const int bRow4 = wn*64 + ((lane >> 4) << 3) + (lane & 7);
    const int bK4   = ((lane >> 3) & 1) * 8;

    #pragma unroll 1
    for (int wsel = 0; wsel < 3; wsel++) {
        float acc[2][8][4] = {};
        #pragma unroll 1
        for (int kc = 0; kc < 2; kc++) {
            __syncthreads();
            const __nv_bfloat16* wh = g_Wth + (size_t)wsel*DOUT*DIN + kc*128;
            const __nv_bfloat16* wl = g_Wtl + (size_t)wsel*DOUT*DIN + kc*128;
            for (int i = tid; i < 128*16; i += 256) {
                int n = i >> 4, c8 = i & 15;
                uint32_t off = (uint32_t)(n*PITB + c8*16);
                size_t go = (size_t)n*DIN + c8*8;
                *reinterpret_cast<uint4*>(Bh + off) =
                    *reinterpret_cast<const uint4*>(wh + go);
                *reinterpret_cast<uint4*>(Bl + off) =
                    *reinterpret_cast<const uint4*>(wl + go);
            }
            __syncthreads();
            uint32_t aBase = kc * 34816;
            #pragma unroll
            for (int term = 0; term < 3; term++) {
                uint32_t sA = ((term == 2) ? sAl : sAh) + aBase;
                uint32_t sB = (term == 1) ? sBl : sBh;
                #pragma unroll
                for (int ks = 0; ks < 8; ks++) {
                    uint32_t af[2][4];
                    #pragma unroll
                    for (int mi = 0; mi < 2; mi++)
                        ldmA(af[mi], sA + ((aRow + mi*16)*PIT + aKb + ks*16)*2);
                    #pragma unroll
                    for (int jj = 0; jj < 4; jj++) {
                        uint32_t bq4[4];
                        ldmB4(bq4, sB + ((bRow4 + jj*16)*PIT + bK4 + ks*16)*2);
                        #pragma unroll
                        for (int mi = 0; mi < 2; mi++) {
                            mma16816(acc[mi][2*jj],     af[mi], bq4);
                            mma16816(acc[mi][2*jj + 1], af[mi], bq4 + 2);
                        }
                    }
                }
            }
        }

        const float* bp = (wsel == 0) ? bq : (wsel == 1) ? bk : bv;
        float bias2[8][2];
        #pragma unroll
        for (int j = 0; j < 8; j++) {
            int c = wn*64 + j*8 + (lane & 3)*2;
            bias2[j][0] = bp[c]; bias2[j][1] = bp[c+1];
        }

        if (wsel < 2) {
            const float s = (wsel == 0) ? 0.0625f : 1.0f;
            __nv_bfloat16* gh = (wsel == 0) ? g_Qh : g_Kh;
            __nv_bfloat16* gl = (wsel == 0) ? g_Ql : g_Kl;
            #pragma unroll
            for (int mi = 0; mi < 2; mi++)
                #pragma unroll
                for (int j = 0; j < 8; j++) {
                    int r = wm*32 + mi*16 + (lane >> 2);
                    int c = wn*64 + j*8 + (lane & 3)*2;
                    float q0 = (acc[mi][j][0] + bias2[j][0]) * s;
                    float q1 = (acc[mi][j][1] + bias2[j][1]) * s;
                    float q2 = (acc[mi][j][2] + bias2[j][0]) * s;
                    float q3 = (acc[mi][j][3] + bias2[j][1]) * s;
                    size_t o0 = ((size_t)(b*Mm + m0 + r))*DOUT + c;
                    size_t o1 = ((size_t)(b*Mm + m0 + r + 8))*DOUT + c;
                    *reinterpret_cast<uint32_t*>(gh + o0) = b2pack(q0, q1);
                    *reinterpret_cast<uint32_t*>(gl + o0) =
                        b2pack(q0 - bhi(q0), q1 - bhi(q1));
                    *reinterpret_cast<uint32_t*>(gh + o1) = b2pack(q2, q3);
                    *reinterpret_cast<uint32_t*>(gl + o1) =
                        b2pack(q2 - bhi(q2), q3 - bhi(q3));
                }
        } else {
            __syncthreads();
            #pragma unroll
            for (int mi = 0; mi < 2; mi++)
                #pragma unroll
                for (int j = 0; j < 8; j++) {
                    int r = wm*32 + mi*16 + (lane >> 2);
                    int c = wn*64 + j*8 + (lane & 3)*2;
                    float v0 = fmaxf(acc[mi][j][0] + bias2[j][0], 0.f);
                    float v1 = fmaxf(acc[mi][j][1] + bias2[j][1], 0.f);
                    float v2 = fmaxf(acc[mi][j][2] + bias2[j][0], 0.f);
                    float v3 = fmaxf(acc[mi][j][3] + bias2[j][1], 0.f);
                    *reinterpret_cast<float2*>(
                        g_V + ((size_t)(b*Mm + m0 + r))*DOUT + c) = make_float2(v0, v1);
                    *reinterpret_cast<float2*>(
                        g_V + ((size_t)(b*Mm + m0 + r + 8))*DOUT + c) = make_float2(v2, v3);
                    Vs[r*132 + c]       = v0;
                    Vs[r*132 + c + 1]   = v1;
                    Vs[(r+8)*132 + c]   = v2;
                    Vs[(r+8)*132 + c+1] = v3;
                }
            __syncthreads();
            int e = tid & 127, half = tid >> 7;
            #pragma unroll
            for (int seg = 0; seg < 2; seg++) {
                int mb = half*64 + seg*32;
                uint32_t hp[16], lp[16];
                #pragma unroll
                for (int t = 0; t < 16; t++) {
                    float x0 = Vs[(mb + 2*t    )*132 + e];
                    float x1 = Vs[(mb + 2*t + 1)*132 + e];
                    hp[t] = b2pack(x0, x1);
                    lp[t] = b2pack(x0 - bhi(x0), x1 - bhi(x1));
                }
                uint4* dh = reinterpret_cast<uint4*>(
                    g_Vth + ((size_t)b*DOUT + e)*Mm + m0 + mb);
                uint4* dl = reinterpret_cast<uint4*>(
                    g_Vtl + ((size_t)b*DOUT + e)*Mm + m0 + mb);
                #pragma unroll
                for (int q = 0; q < 4; q++) {
                    dh[q] = make_uint4(hp[4*q],hp[4*q+1],hp[4*q+2],hp[4*q+3]);
                    dl[q] = make_uint4(lp[4*q],lp[4*q+1],lp[4*q+2],lp[4*q+3]);
                }
            }
        }
    }
}

// ---------------------------------------------------------------------------
// attnF: FUSED QK^T + softmax + AV + l2norm. 256 threads, 8 warps (8m x 1n),
// warp tile 16 rows x 64 keys; P stays in registers between the two MMAs.
// smem: Qh|Ql 69632 + 2 stages x (K hi/lo 34816 + Vt hi/lo 36864) = 212992.
// ---------------------------------------------------------------------------
__global__ __launch_bounds__(256, 1)
void attnF_kernel(float* __restrict__ att, float* __restrict__ out)
{
    extern __shared__ char smraw[];
    const int tid = threadIdx.x, lane = tid & 31, wid = tid >> 5;
    const int b = blockIdx.y, m0 = blockIdx.x * 128;

    char* Qh = smraw;
    char* Ql = smraw + 34816;
    const uint32_t sQh = cvta_smem(Qh), sQl = cvta_smem(Ql);
    const uint32_t sStg = cvta_smem(smraw + 69632);

    auto issue = [&](int ch, int st) {
        const uint32_t kb = sStg + st*71680;
        #pragma unroll
        for (int t = 0; t < 8; t++) {       // K: 64 rows x 256B x2 tiles
            int i = tid + t*256;
            int tile = i >> 10, row = (i >> 4) & 63, p = i & 15;
            const __nv_bfloat16* src = (tile ? g_Kl : g_Kh)
                + ((size_t)(b*Mm + ch*64 + row))*DOUT + p*8;
            CPA(kb + tile*17408 + row*PITB + p*16, src);
        }
        const uint32_t vb = kb + 34816;
        #pragma unroll
        for (int t = 0; t < 8; t++) {       // Vt: 128 rows x 128B x2 tiles
            int i = tid + t*256;
            int tile = i >> 10, row = (i >> 3) & 127, p = i & 7;
            const __nv_bfloat16* src = (tile ? g_Vtl : g_Vth)
                + ((size_t)(b*DOUT + row))*Mm + ch*64 + p*8;
            CPA(vb + tile*18432 + row*P64B + p*16, src);
        }
        CPC();
    };

    issue(0, 0);

    {   // Q resident (hi/lo), pitch 272
        const uint4* qh = reinterpret_cast<const uint4*>(g_Qh + ((size_t)b*Mm + m0)*DOUT);
        const uint4* ql = reinterpret_cast<const uint4*>(g_Ql + ((size_t)b*Mm + m0)*DOUT);
        for (int i = tid; i < 128*16; i += 256) {
            int row = i >> 4, c8 = i & 15;
            *reinterpret_cast<uint4*>(Qh + row*PITB + c8*16) = qh[i];
            *reinterpret_cast<uint4*>(Ql + row*PITB + c8*16) = ql[i];
        }
    }

    const int aRow  = wid*16 + (lane & 15);
    const int aKb   = (lane >> 4) * 8;
    const int bRow4 = ((lane >> 4) << 3) + (lane & 7);
    const int bK4   = ((lane >> 3) & 1) * 8;

    float av[16][4] = {};
    float rsumA = 0.f, rsumB = 0.f;
    const int rloc = lane >> 2;              // row within warp tile (and +8)

    #pragma unroll 1
    for (int ch = 0; ch < 32; ch++) {
        int st = ch & 1;
        if (ch < 31) issue(ch + 1, st ^ 1);
        if (ch < 31) { CPW1(); } else { CPW0(); }
        __syncthreads();

        const uint32_t kh = sStg + st*71680;
        const uint32_t kl = kh + 17408;
        const uint32_t vh = kh + 34816;
        const uint32_t vl = kh + 53248;

        // ---- S = Q K^T (3-term split), warp tile 16 x 64 ----
        float s[8][4] = {};
        #pragma unroll
        for (int term = 0; term < 3; term++) {
            uint32_t sA = (term == 2) ? sQl : sQh;
            uint32_t sB = (term == 1) ? kl : kh;
            #pragma unroll
            for (int kt = 0; kt < 8; kt++) {
                uint32_t af[4];
                ldmA(af, sA + (aRow*PIT + aKb + kt*16)*2);
                #pragma unroll
                for (int jj = 0; jj < 4; jj++) {
                    uint32_t bq4[4];
                    ldmB4(bq4, sB + (bRow4 + jj*16)*PITB + (bK4 + kt*16)*2);
                    mma16816(s[2*jj],     af, bq4);
                    mma16816(s[2*jj + 1], af, bq4 + 2);
                }
            }
        }

        // ---- exp (shift-free; clamp for paranoia) + row sums ----
        float psA = 0.f, psB = 0.f;
        #pragma unroll
        for (int j = 0; j < 8; j++) {
            s[j][0] = __expf(fminf(s[j][0], 80.f));
            s[j][1] = __expf(fminf(s[j][1], 80.f));
            s[j][2] = __expf(fminf(s[j][2], 80.f));
            s[j][3] = __expf(fminf(s[j][3], 80.f));
            psA += s[j][0] + s[j][1];
            psB += s[j][2] + s[j][3];
        }
        psA += __shfl_xor_sync(0xffffffffu, psA, 1);
        psA += __shfl_xor_sync(0xffffffffu, psA, 2);
        psB += __shfl_xor_sync(0xffffffffu, psB, 1);
        psB += __shfl_xor_sync(0xffffffffu, psB, 2);
        rsumA += psA;
        rsumB += psB;

        // ---- store unnormalized exp to att ----
        {
            float* a0 = att + ((size_t)(b*Mm + m0 + wid*16 + rloc))*Mm
                            + ch*64 + (lane & 3)*2;
            float* a1 = a0 + (size_t)8*Mm;
            #pragma unroll
            for (int j = 0; j < 8; j++) {
                *reinterpret_cast<float2*>(a0 + j*8) = make_float2(s[j][0], s[j][1]);
                *reinterpret_cast<float2*>(a1 + j*8) = make_float2(s[j][2], s[j][3]);
            }
        }

        // ---- AV += P @ V^T : A-fragments straight from registers ----
        #pragma unroll
        for (int kt = 0; kt < 4; kt++) {
            const int j0 = 2*kt, j1 = 2*kt + 1;
            uint32_t afh[4], afl[4];
            afh[0] = b2pack(s[j0][0], s[j0][1]);
            afh[1] = b2pack(s[j0][2], s[j0][3]);
            afh[2] = b2pack(s[j1][0], s[j1][1]);
            afh[3] = b2pack(s[j1][2], s[j1][3]);
            afl[0] = b2pack(s[j0][0]-bhi(s[j0][0]), s[j0][1]-bhi(s[j0][1]));
            afl[1] = b2pack(s[j0][2]-bhi(s[j0][2]), s[j0][3]-bhi(s[j0][3]));
            afl[2] = b2pack(s[j1][0]-bhi(s[j1][0]), s[j1][1]-bhi(s[j1][1]));
            afl[3] = b2pack(s[j1][2]-bhi(s[j1][2]), s[j1][3]-bhi(s[j1][3]));
            #pragma unroll
            for (int jj = 0; jj < 8; jj++) {
                uint32_t bh4[4], bl4[4];
                ldmB4(bh4, vh + (bRow4 + jj*16)*P64B + (bK4 + kt*16)*2);
                ldmB4(bl4, vl + (bRow4 + jj*16)*P64B + (bK4 + kt*16)*2);
                mma16816(av[2*jj],     afh, bh4);
                mma16816(av[2*jj + 1], afh, bh4 + 2);
                mma16816(av[2*jj],     afh, bl4);
                mma16816(av[2*jj + 1], afh, bl4 + 2);
                mma16816(av[2*jj],     afl, bh4);
                mma16816(av[2*jj + 1], afl, bh4 + 2);
            }
        }
        __syncthreads();   // all warps done with stage st before re-fill
    }

    // ---- epilogue: AV/sum, out = l2norm(V + l2norm(AV)) ----
    float invA = 1.f / rsumA, invB = 1.f / rsumB;
    float ssA = 0.f, ssB = 0.f;
    #pragma unroll
    for (int jn = 0; jn < 16; jn++) {
        av[jn][0] *= invA; av[jn][1] *= invA;
        av[jn][2] *= invB; av[jn][3] *= invB;
        ssA += av[jn][0]*av[jn][0] + av[jn][1]*av[jn][1];
        ssB += av[jn][2]*av[jn][2] + av[jn][3]*av[jn][3];
    }
    ssA += __shfl_xor_sync(0xffffffffu, ssA, 1);
    ssA += __shfl_xor_sync(0xffffffffu, ssA, 2);
    ssB += __shfl_xor_sync(0xffffffffu, ssB, 1);
    ssB += __shfl_xor_sync(0xffffffffu, ssB, 2);
    float n1A = rsqrtf(fmaxf(ssA, 1e-12f));
    float n1B = rsqrtf(fmaxf(ssB, 1e-12f));

    const float* v0p = g_V + ((size_t)(b*Mm + m0 + wid*16 + rloc))*DOUT + (lane & 3)*2;
    const float* v1p = v0p + 8*DOUT;
    float ss2A = 0.f, ss2B = 0.f;
    #pragma unroll
    for (int jn = 0; jn < 16; jn++) {
        float2 v0 = *reinterpret_cast<const float2*>(v0p + jn*8);
        float2 v1 = *reinterpret_cast<const float2*>(v1p + jn*8);
        av[jn][0] = v0.x + av[jn][0]*n1A;
        av[jn][1] = v0.y + av[jn][1]*n1A;
        av[jn][2] = v1.x + av[jn][2]*n1B;
        av[jn][3] = v1.y + av[jn][3]*n1B;
        ss2A += av[jn][0]*av[jn][0] + av[jn][1]*av[jn][1];
        ss2B += av[jn][2]*av[jn][2] + av[jn][3]*av[jn][3];
    }
    ss2A += __shfl_xor_sync(0xffffffffu, ss2A, 1);
    ss2A += __shfl_xor_sync(0xffffffffu, ss2A, 2);
    ss2B += __shfl_xor_sync(0xffffffffu, ss2B, 1);
    ss2B += __shfl_xor_sync(0xffffffffu, ss2B, 2);
    float n2A = rsqrtf(fmaxf(ss2A, 1e-12f));
    float n2B = rsqrtf(fmaxf(ss2B, 1e-12f));

    {
        float* o0 = out + ((size_t)(b*Mm + m0 + wid*16 + rloc))*DOUT + (lane & 3)*2;
        float* o1 = o0 + 8*DOUT;
        #pragma unroll
        for (int jn = 0; jn < 16; jn++) {
            *reinterpret_cast<float2*>(o0 + jn*8) =
                make_float2(av[jn][0]*n2A, av[jn][1]*n2A);
            *reinterpret_cast<float2*>(o1 + jn*8) =
                make_float2(av[jn][2]*n2B, av[jn][3]*n2B);
        }
    }

    // ---- pass 2: normalize att in place ----
    float* invS = reinterpret_cast<float*>(smraw);   // Q area dead now
    if ((lane & 3) == 0) {
        invS[wid*16 + rloc]     = invA;
        invS[wid*16 + rloc + 8] = invB;
    }
    __syncthreads();
    #pragma unroll 1
    for (int rr = 0; rr < 16; rr++) {
        int row = wid*16 + rr;
        float inv = invS[row];
        float4* ar = reinterpret_cast<float4*>(att + ((size_t)(b*Mm + m0 + row))*Mm);
        #pragma unroll
        for (int q = 0; q < 16; q++) {
            float4 v = ar[lane + q*32];
            v.x *= inv; v.y *= inv; v.z *= inv; v.w *= inv;
            ar[lane + q*32] = v;
        }
    }
}

// ---------------------------------------------------------------------------
extern "C" void kernel_launch(void* const* d_in, const int* in_sizes, int n_in,
                              void* d_out, int out_size)
{
    const float* Y   = (const float*)d_in[0];
    const int*   idx = (const int*)  d_in[1];
    const float* Wq  = (const float*)d_in[2];
    const float* bq  = (const float*)d_in[3];
    const float* Wk  = (const float*)d_in[4];
    const float* bk  = (const float*)d_in[5];
    const float* Wv  = (const float*)d_in[6];
    const float* bv  = (const float*)d_in[7];

    float* out = (float*)d_out;                       // [8,2048,128]
    float* att = out + (size_t)Bb*Mm*DOUT;            // [8,2048,2048]

    const int smemP = 208896;
    const int smemF = 212992;

    cudaFuncSetAttribute(projmma_kernel, cudaFuncAttributeMaxDynamicSharedMemorySize, smemP);
    cudaFuncSetAttribute(attnF_kernel,   cudaFuncAttributeMaxDynamicSharedMemorySize, smemF);

    prep_kernel<<<3, 256>>>(Wq, Wk, Wv);
    projmma_kernel<<<(Bb*Mm)/128, 256, smemP>>>(Y, idx, bq, bk, bv);
    attnF_kernel<<<dim3(Mm/128, Bb), 256, smemF>>>(att, out);
}

// round 13
// speedup vs baseline: 1.3156x; 1.0596x over previous
#include <cuda_runtime.h>
#include <cuda_bf16.h>
#include <cstdint>

#define Bb   8
#define Nn   4096
#define Mm   2048
#define DIN  256
#define DOUT 128

__device__ __nv_bfloat16 g_Qh [Bb*Mm*DOUT];
__device__ __nv_bfloat16 g_Ql [Bb*Mm*DOUT];
__device__ __nv_bfloat16 g_Kh [Bb*Mm*DOUT];
__device__ __nv_bfloat16 g_Kl [Bb*Mm*DOUT];
__device__ float         g_V  [Bb*Mm*DOUT];
__device__ __nv_bfloat16 g_Vth[Bb*DOUT*Mm];    // [b][e][m]
__device__ __nv_bfloat16 g_Vtl[Bb*DOUT*Mm];
__device__ __nv_bfloat16 g_Wth[3*DOUT*DIN];    // [wsel][n][k]
__device__ __nv_bfloat16 g_Wtl[3*DOUT*DIN];

// ---------------- helpers ----------------
__device__ __forceinline__ uint32_t cvta_smem(const void* p) {
    uint32_t a;
    asm("{ .reg .u64 t; cvta.to.shared.u64 t, %1; cvt.u32.u64 %0, t; }" : "=r"(a) : "l"(p));
    return a;
}
__device__ __forceinline__ uint32_t b2pack(float a, float b) {
    uint16_t la = __bfloat16_as_ushort(__float2bfloat16(a));
    uint16_t lb = __bfloat16_as_ushort(__float2bfloat16(b));
    return (uint32_t)la | ((uint32_t)lb << 16);
}
__device__ __forceinline__ float bhi(float x) {
    return __bfloat162float(__float2bfloat16(x));
}
__device__ __forceinline__ void ldmA(uint32_t a[4], uint32_t addr) {
    asm volatile("ldmatrix.sync.aligned.m8n8.x4.shared.b16 {%0,%1,%2,%3}, [%4];"
        : "=r"(a[0]),"=r"(a[1]),"=r"(a[2]),"=r"(a[3]) : "r"(addr));
}
__device__ __forceinline__ void ldmB4(uint32_t b[4], uint32_t addr) {
    asm volatile("ldmatrix.sync.aligned.m8n8.x4.shared.b16 {%0,%1,%2,%3}, [%4];"
        : "=r"(b[0]),"=r"(b[1]),"=r"(b[2]),"=r"(b[3]) : "r"(addr));
}
__device__ __forceinline__ void mma16816(float c[4], const uint32_t a[4], const uint32_t b[2]) {
    asm volatile("mma.sync.aligned.m16n8k16.row.col.f32.bf16.bf16.f32 "
        "{%0,%1,%2,%3}, {%4,%5,%6,%7}, {%8,%9}, {%0,%1,%2,%3};"
        : "+f"(c[0]),"+f"(c[1]),"+f"(c[2]),"+f"(c[3])
        : "r"(a[0]),"r"(a[1]),"r"(a[2]),"r"(a[3]), "r"(b[0]),"r"(b[1]));
}
#define CPA(d, s) asm volatile("cp.async.cg.shared.global [%0], [%1], 16;" :: "r"(d), "l"(s))
#define CPC()     asm volatile("cp.async.commit_group;" ::: "memory")
#define CPW1()    asm volatile("cp.async.wait_group 1;" ::: "memory")
#define CPW0()    asm volatile("cp.async.wait_group 0;" ::: "memory")

#define PIT 136
#define PITB 272
#define P64B 144

// ---------------------------------------------------------------------------
// prep: W[k][n] fp32 -> W^T[n][k] bf16 hi/lo. 48 blocks (16 per matrix,
// 8 n-rows each) so the transpose is spread across SMs instead of 3.
// ---------------------------------------------------------------------------
__global__ void prep_kernel(const float* __restrict__ Wq,
                            const float* __restrict__ Wk,
                            const float* __restrict__ Wv)
{
    const int wsel  = blockIdx.x >> 4;          // 0..2
    const int slice = blockIdx.x & 15;          // 0..15 -> 8 n-rows each
    const float* W = (wsel == 0) ? Wq : (wsel == 1) ? Wk : Wv;
    __nv_bfloat16* dh = g_Wth + wsel * DOUT * DIN;
    __nv_bfloat16* dl = g_Wtl + wsel * DOUT * DIN;
    const int n0 = slice * 8;
    for (int i = threadIdx.x; i < 8 * (DIN/2); i += 256) {
        int n = n0 + (i >> 7), k = (i & 127) * 2;
        float x0 = W[(size_t)k*DOUT + n];
        float x1 = W[(size_t)(k+1)*DOUT + n];
        *reinterpret_cast<uint32_t*>(dh + (size_t)n*DIN + k) = b2pack(x0, x1);
        *reinterpret_cast<uint32_t*>(dl + (size_t)n*DIN + k) =
            b2pack(x0 - bhi(x0), x1 - bhi(x1));
    }
}

// ---------------------------------------------------------------------------
// projmma (round-9 proven): 256 threads, 8 warps (4m x 2n), warp tile 32x64.
// ---------------------------------------------------------------------------
__global__ __launch_bounds__(256, 1)
void projmma_kernel(const float* __restrict__ Y, const int* __restrict__ idx,
                    const float* __restrict__ bq, const float* __restrict__ bk,
                    const float* __restrict__ bv)
{
    extern __shared__ char smraw[];
    char* Ah = smraw;                    // 2 k-chunks x 34816
    char* Al = smraw + 69632;
    char* Bh = smraw + 139264;
    char* Bl = smraw + 174080;
    float* Vs = reinterpret_cast<float*>(Bh);
    __shared__ int idxs[128];

    const int tid = threadIdx.x, lane = tid & 31, wid = tid >> 5;
    const int wm = wid >> 1, wn = wid & 1;
    const int row0 = blockIdx.x * 128;
    const int b    = row0 / Mm;
    const int m0   = row0 % Mm;

    if (tid < 128) idxs[tid] = idx[b*Mm + m0 + tid];
    __syncthreads();

    for (int i = tid; i < 128*64; i += 256) {
        int row = i >> 6, c4 = i & 63;
        float4 y = *reinterpret_cast<const float4*>(
            Y + ((size_t)b*Nn + idxs[row])*DIN + c4*4);
        int kc = c4 >> 5;
        uint32_t off = (uint32_t)(kc*34816 + row*PITB + (c4 & 31)*8);
        *reinterpret_cast<uint2*>(Ah + off) =
            make_uint2(b2pack(y.x, y.y), b2pack(y.z, y.w));
        *reinterpret_cast<uint2*>(Al + off) =
            make_uint2(b2pack(y.x-bhi(y.x), y.y-bhi(y.y)),
                       b2pack(y.z-bhi(y.z), y.w-bhi(y.w)));
    }

    const uint32_t sAh = cvta_smem(Ah), sAl = cvta_smem(Al);
    const uint32_t sBh = cvta_smem(Bh), sBl = cvta_smem(Bl);

    const int aRow  = wm*32 + (lane & 15);
    const int aKb   = (lane >> 4) * 8;
    const int bRow4 = wn*64 + ((lane >> 4) << 3) + (lane & 7);
    const int bK4   = ((lane >> 3) & 1) * 8;

    #pragma unroll 1
    for (int wsel = 0; wsel < 3; wsel++) {
        float acc[2][8][4] = {};
        #pragma unroll 1
        for (int kc = 0; kc < 2; kc++) {
            __syncthreads();
            const __nv_bfloat16* wh = g_Wth + (size_t)wsel*DOUT*DIN + kc*128;
            const __nv_bfloat16* wl = g_Wtl + (size_t)wsel*DOUT*DIN + kc*128;
            for (int i = tid; i < 128*16; i += 256) {
                int n = i >> 4, c8 = i & 15;
                uint32_t off = (uint32_t)(n*PITB + c8*16);
                size_t go = (size_t)n*DIN + c8*8;
                *reinterpret_cast<uint4*>(Bh + off) =
                    *reinterpret_cast<const uint4*>(wh + go);
                *reinterpret_cast<uint4*>(Bl + off) =
                    *reinterpret_cast<const uint4*>(wl + go);
            }
            __syncthreads();
            uint32_t aBase = kc * 34816;
            #pragma unroll
            for (int term = 0; term < 3; term++) {
                uint32_t sA = ((term == 2) ? sAl : sAh) + aBase;
                uint32_t sB = (term == 1) ? sBl : sBh;
                #pragma unroll
                for (int ks = 0; ks < 8; ks++) {
                    uint32_t af[2][4];
                    #pragma unroll
                    for (int mi = 0; mi < 2; mi++)
                        ldmA(af[mi], sA + ((aRow + mi*16)*PIT + aKb + ks*16)*2);
                    #pragma unroll
                    for (int jj = 0; jj < 4; jj++) {
                        uint32_t bq4[4];
                        ldmB4(bq4, sB + ((bRow4 + jj*16)*PIT + bK4 + ks*16)*2);
                        #pragma unroll
                        for (int mi = 0; mi < 2; mi++) {
                            mma16816(acc[mi][2*jj],     af[mi], bq4);
                            mma16816(acc[mi][2*jj + 1], af[mi], bq4 + 2);
                        }
                    }
                }
            }
        }

        const float* bp = (wsel == 0) ? bq : (wsel == 1) ? bk : bv;
        float bias2[8][2];
        #pragma unroll
        for (int j = 0; j < 8; j++) {
            int c = wn*64 + j*8 + (lane & 3)*2;
            bias2[j][0] = bp[c]; bias2[j][1] = bp[c+1];
        }

        if (wsel < 2) {
            const float s = (wsel == 0) ? 0.0625f : 1.0f;
            __nv_bfloat16* gh = (wsel == 0) ? g_Qh : g_Kh;
            __nv_bfloat16* gl = (wsel == 0) ? g_Ql : g_Kl;
            #pragma unroll
            for (int mi = 0; mi < 2; mi++)
                #pragma unroll
                for (int j = 0; j < 8; j++) {
                    int r = wm*32 + mi*16 + (lane >> 2);
                    int c = wn*64 + j*8 + (lane & 3)*2;
                    float q0 = (acc[mi][j][0] + bias2[j][0]) * s;
                    float q1 = (acc[mi][j][1] + bias2[j][1]) * s;
                    float q2 = (acc[mi][j][2] + bias2[j][0]) * s;
                    float q3 = (acc[mi][j][3] + bias2[j][1]) * s;
                    size_t o0 = ((size_t)(b*Mm + m0 + r))*DOUT + c;
                    size_t o1 = ((size_t)(b*Mm + m0 + r + 8))*DOUT + c;
                    *reinterpret_cast<uint32_t*>(gh + o0) = b2pack(q0, q1);
                    *reinterpret_cast<uint32_t*>(gl + o0) =
                        b2pack(q0 - bhi(q0), q1 - bhi(q1));
                    *reinterpret_cast<uint32_t*>(gh + o1) = b2pack(q2, q3);
                    *reinterpret_cast<uint32_t*>(gl + o1) =
                        b2pack(q2 - bhi(q2), q3 - bhi(q3));
                }
        } else {
            __syncthreads();
            #pragma unroll
            for (int mi = 0; mi < 2; mi++)
                #pragma unroll
                for (int j = 0; j < 8; j++) {
                    int r = wm*32 + mi*16 + (lane >> 2);
                    int c = wn*64 + j*8 + (lane & 3)*2;
                    float v0 = fmaxf(acc[mi][j][0] + bias2[j][0], 0.f);
                    float v1 = fmaxf(acc[mi][j][1] + bias2[j][1], 0.f);
                    float v2 = fmaxf(acc[mi][j][2] + bias2[j][0], 0.f);
                    float v3 = fmaxf(acc[mi][j][3] + bias2[j][1], 0.f);
                    *reinterpret_cast<float2*>(
                        g_V + ((size_t)(b*Mm + m0 + r))*DOUT + c) = make_float2(v0, v1);
                    *reinterpret_cast<float2*>(
                        g_V + ((size_t)(b*Mm + m0 + r + 8))*DOUT + c) = make_float2(v2, v3);
                    Vs[r*132 + c]       = v0;
                    Vs[r*132 + c + 1]   = v1;
                    Vs[(r+8)*132 + c]   = v2;
                    Vs[(r+8)*132 + c+1] = v3;
                }
            __syncthreads();
            int e = tid & 127, half = tid >> 7;
            #pragma unroll
            for (int seg = 0; seg < 2; seg++) {
                int mb = half*64 + seg*32;
                uint32_t hp[16], lp[16];
                #pragma unroll
                for (int t = 0; t < 16; t++) {
                    float x0 = Vs[(mb + 2*t    )*132 + e];
                    float x1 = Vs[(mb + 2*t + 1)*132 + e];
                    hp[t] = b2pack(x0, x1);
                    lp[t] = b2pack(x0 - bhi(x0), x1 - bhi(x1));
                }
                uint4* dh = reinterpret_cast<uint4*>(
                    g_Vth + ((size_t)b*DOUT + e)*Mm + m0 + mb);
                uint4* dl = reinterpret_cast<uint4*>(
                    g_Vtl + ((size_t)b*DOUT + e)*Mm + m0 + mb);
                #pragma unroll
                for (int q = 0; q < 4; q++) {
                    dh[q] = make_uint4(hp[4*q],hp[4*q+1],hp[4*q+2],hp[4*q+3]);
                    dl[q] = make_uint4(lp[4*q],lp[4*q+1],lp[4*q+2],lp[4*q+3]);
                }
            }
        }
    }
}

// ---------------------------------------------------------------------------
// attnF: FUSED QK^T + softmax + AV + l2norm (round-12 proven, unchanged).
// ---------------------------------------------------------------------------
__global__ __launch_bounds__(256, 1)
void attnF_kernel(float* __restrict__ att, float* __restrict__ out)
{
    extern __shared__ char smraw[];
    const int tid = threadIdx.x, lane = tid & 31, wid = tid >> 5;
    const int b = blockIdx.y, m0 = blockIdx.x * 128;

    char* Qh = smraw;
    char* Ql = smraw + 34816;
    const uint32_t sQh = cvta_smem(Qh), sQl = cvta_smem(Ql);
    const uint32_t sStg = cvta_smem(smraw + 69632);

    auto issue = [&](int ch, int st) {
        const uint32_t kb = sStg + st*71680;
        #pragma unroll
        for (int t = 0; t < 8; t++) {
            int i = tid + t*256;
            int tile = i >> 10, row = (i >> 4) & 63, p = i & 15;
            const __nv_bfloat16* src = (tile ? g_Kl : g_Kh)
                + ((size_t)(b*Mm + ch*64 + row))*DOUT + p*8;
            CPA(kb + tile*17408 + row*PITB + p*16, src);
        }
        const uint32_t vb = kb + 34816;
        #pragma unroll
        for (int t = 0; t < 8; t++) {
            int i = tid + t*256;
            int tile = i >> 10, row = (i >> 3) & 127, p = i & 7;
            const __nv_bfloat16* src = (tile ? g_Vtl : g_Vth)
                + ((size_t)(b*DOUT + row))*Mm + ch*64 + p*8;
            CPA(vb + tile*18432 + row*P64B + p*16, src);
        }
        CPC();
    };

    issue(0, 0);

    {
        const uint4* qh = reinterpret_cast<const uint4*>(g_Qh + ((size_t)b*Mm + m0)*DOUT);
        const uint4* ql = reinterpret_cast<const uint4*>(g_Ql + ((size_t)b*Mm + m0)*DOUT);
        for (int i = tid; i < 128*16; i += 256) {
            int row = i >> 4, c8 = i & 15;
            *reinterpret_cast<uint4*>(Qh + row*PITB + c8*16) = qh[i];
            *reinterpret_cast<uint4*>(Ql + row*PITB + c8*16) = ql[i];
        }
    }

    const int aRow  = wid*16 + (lane & 15);
    const int aKb   = (lane >> 4) * 8;
    const int bRow4 = ((lane >> 4) << 3) + (lane & 7);
    const int bK4   = ((lane >> 3) & 1) * 8;

    float av[16][4] = {};
    float rsumA = 0.f, rsumB = 0.f;
    const int rloc = lane >> 2;

    #pragma unroll 1
    for (int ch = 0; ch < 32; ch++) {
        int st = ch & 1;
        if (ch < 31) issue(ch + 1, st ^ 1);
        if (ch < 31) { CPW1(); } else { CPW0(); }
        __syncthreads();

        const uint32_t kh = sStg + st*71680;
        const uint32_t kl = kh + 17408;
        const uint32_t vh = kh + 34816;
        const uint32_t vl = kh + 53248;

        float s[8][4] = {};
        #pragma unroll
        for (int term = 0; term < 3; term++) {
            uint32_t sA = (term == 2) ? sQl : sQh;
            uint32_t sB = (term == 1) ? kl : kh;
            #pragma unroll
            for (int kt = 0; kt < 8; kt++) {
                uint32_t af[4];
                ldmA(af, sA + (aRow*PIT + aKb + kt*16)*2);
                #pragma unroll
                for (int jj = 0; jj < 4; jj++) {
                    uint32_t bq4[4];
                    ldmB4(bq4, sB + (bRow4 + jj*16)*PITB + (bK4 + kt*16)*2);
                    mma16816(s[2*jj],     af, bq4);
                    mma16816(s[2*jj + 1], af, bq4 + 2);
                }
            }
        }

        float psA = 0.f, psB = 0.f;
        #pragma unroll
        for (int j = 0; j < 8; j++) {
            s[j][0] = __expf(fminf(s[j][0], 80.f));
            s[j][1] = __expf(fminf(s[j][1], 80.f));
            s[j][2] = __expf(fminf(s[j][2], 80.f));
            s[j][3] = __expf(fminf(s[j][3], 80.f));
            psA += s[j][0] + s[j][1];
            psB += s[j][2] + s[j][3];
        }
        psA += __shfl_xor_sync(0xffffffffu, psA, 1);
        psA += __shfl_xor_sync(0xffffffffu, psA, 2);
        psB += __shfl_xor_sync(0xffffffffu, psB, 1);
        psB += __shfl_xor_sync(0xffffffffu, psB, 2);
        rsumA += psA;
        rsumB += psB;

        {
            float* a0 = att + ((size_t)(b*Mm + m0 + wid*16 + rloc))*Mm
                            + ch*64 + (lane & 3)*2;
            float* a1 = a0 + (size_t)8*Mm;
            #pragma unroll
            for (int j = 0; j < 8; j++) {
                *reinterpret_cast<float2*>(a0 + j*8) = make_float2(s[j][0], s[j][1]);
                *reinterpret_cast<float2*>(a1 + j*8) = make_float2(s[j][2], s[j][3]);
            }
        }

        #pragma unroll
        for (int kt = 0; kt < 4; kt++) {
            const int j0 = 2*kt, j1 = 2*kt + 1;
            uint32_t afh[4], afl[4];
            afh[0] = b2pack(s[j0][0], s[j0][1]);
            afh[1] = b2pack(s[j0][2], s[j0][3]);
            afh[2] = b2pack(s[j1][0], s[j1][1]);
            afh[3] = b2pack(s[j1][2], s[j1][3]);
            afl[0] = b2pack(s[j0][0]-bhi(s[j0][0]), s[j0][1]-bhi(s[j0][1]));
            afl[1] = b2pack(s[j0][2]-bhi(s[j0][2]), s[j0][3]-bhi(s[j0][3]));
            afl[2] = b2pack(s[j1][0]-bhi(s[j1][0]), s[j1][1]-bhi(s[j1][1]));
            afl[3] = b2pack(s[j1][2]-bhi(s[j1][2]), s[j1][3]-bhi(s[j1][3]));
            #pragma unroll
            for (int jj = 0; jj < 8; jj++) {
                uint32_t bh4[4], bl4[4];
                ldmB4(bh4, vh + (bRow4 + jj*16)*P64B + (bK4 + kt*16)*2);
                ldmB4(bl4, vl + (bRow4 + jj*16)*P64B + (bK4 + kt*16)*2);
                mma16816(av[2*jj],     afh, bh4);
                mma16816(av[2*jj + 1], afh, bh4 + 2);
                mma16816(av[2*jj],     afh, bl4);
                mma16816(av[2*jj + 1], afh, bl4 + 2);
                mma16816(av[2*jj],     afl, bh4);
                mma16816(av[2*jj + 1], afl, bh4 + 2);
            }
        }
        __syncthreads();
    }

    float invA = 1.f / rsumA, invB = 1.f / rsumB;
    float ssA = 0.f, ssB = 0.f;
    #pragma unroll
    for (int jn = 0; jn < 16; jn++) {
        av[jn][0] *= invA; av[jn][1] *= invA;
        av[jn][2] *= invB; av[jn][3] *= invB;
        ssA += av[jn][0]*av[jn][0] + av[jn][1]*av[jn][1];
        ssB += av[jn][2]*av[jn][2] + av[jn][3]*av[jn][3];
    }
    ssA += __shfl_xor_sync(0xffffffffu, ssA, 1);
    ssA += __shfl_xor_sync(0xffffffffu, ssA, 2);
    ssB += __shfl_xor_sync(0xffffffffu, ssB, 1);
    ssB += __shfl_xor_sync(0xffffffffu, ssB, 2);
    float n1A = rsqrtf(fmaxf(ssA, 1e-12f));
    float n1B = rsqrtf(fmaxf(ssB, 1e-12f));

    const float* v0p = g_V + ((size_t)(b*Mm + m0 + wid*16 + rloc))*DOUT + (lane & 3)*2;
    const float* v1p = v0p + 8*DOUT;
    float ss2A = 0.f, ss2B = 0.f;
    #pragma unroll
    for (int jn = 0; jn < 16; jn++) {
        float2 v0 = *reinterpret_cast<const float2*>(v0p + jn*8);
        float2 v1 = *reinterpret_cast<const float2*>(v1p + jn*8);
        av[jn][0] = v0.x + av[jn][0]*n1A;
        av[jn][1] = v0.y + av[jn][1]*n1A;
        av[jn][2] = v1.x + av[jn][2]*n1B;
        av[jn][3] = v1.y + av[jn][3]*n1B;
        ss2A += av[jn][0]*av[jn][0] + av[jn][1]*av[jn][1];
        ss2B += av[jn][2]*av[jn][2] + av[jn][3]*av[jn][3];
    }
    ss2A += __shfl_xor_sync(0xffffffffu, ss2A, 1);
    ss2A += __shfl_xor_sync(0xffffffffu, ss2A, 2);
    ss2B += __shfl_xor_sync(0xffffffffu, ss2B, 1);
    ss2B += __shfl_xor_sync(0xffffffffu, ss2B, 2);
    float n2A = rsqrtf(fmaxf(ss2A, 1e-12f));
    float n2B = rsqrtf(fmaxf(ss2B, 1e-12f));

    {
        float* o0 = out + ((size_t)(b*Mm + m0 + wid*16 + rloc))*DOUT + (lane & 3)*2;
        float* o1 = o0 + 8*DOUT;
        #pragma unroll
        for (int jn = 0; jn < 16; jn++) {
            *reinterpret_cast<float2*>(o0 + jn*8) =
                make_float2(av[jn][0]*n2A, av[jn][1]*n2A);
            *reinterpret_cast<float2*>(o1 + jn*8) =
                make_float2(av[jn][2]*n2B, av[jn][3]*n2B);
        }
    }

    float* invS = reinterpret_cast<float*>(smraw);
    if ((lane & 3) == 0) {
        invS[wid*16 + rloc]     = invA;
        invS[wid*16 + rloc + 8] = invB;
    }
    __syncthreads();
    #pragma unroll 1
    for (int rr = 0; rr < 16; rr++) {
        int row = wid*16 + rr;
        float inv = invS[row];
        float4* ar = reinterpret_cast<float4*>(att + ((size_t)(b*Mm + m0 + row))*Mm);
        #pragma unroll
        for (int q = 0; q < 16; q++) {
            float4 v = ar[lane + q*32];
            v.x *= inv; v.y *= inv; v.z *= inv; v.w *= inv;
            ar[lane + q*32] = v;
        }
    }
}

// ---------------------------------------------------------------------------
extern "C" void kernel_launch(void* const* d_in, const int* in_sizes, int n_in,
                              void* d_out, int out_size)
{
    const float* Y   = (const float*)d_in[0];
    const int*   idx = (const int*)  d_in[1];
    const float* Wq  = (const float*)d_in[2];
    const float* bq  = (const float*)d_in[3];
    const float* Wk  = (const float*)d_in[4];
    const float* bk  = (const float*)d_in[5];
    const float* Wv  = (const float*)d_in[6];
    const float* bv  = (const float*)d_in[7];

    float* out = (float*)d_out;                       // [8,2048,128]
    float* att = out + (size_t)Bb*Mm*DOUT;            // [8,2048,2048]

    const int smemP = 208896;
    const int smemF = 212992;

    cudaFuncSetAttribute(projmma_kernel, cudaFuncAttributeMaxDynamicSharedMemorySize, smemP);
    cudaFuncSetAttribute(attnF_kernel,   cudaFuncAttributeMaxDynamicSharedMemorySize, smemF);

    prep_kernel<<<48, 256>>>(Wq, Wk, Wv);
    projmma_kernel<<<(Bb*Mm)/128, 256, smemP>>>(Y, idx, bq, bk, bv);
    attnF_kernel<<<dim3(Mm/128, Bb), 256, smemF>>>(att, out);
}